// round 7
// baseline (speedup 1.0000x reference)
#include <cuda_runtime.h>
#include <cuda_bf16.h>
#include <math.h>

// ---------------------------------------------------------------------------
// ViT encoder: B=8, N=1024 tokens, D=768, 8 layers, 12 heads x 64, MLP 3072.
// tf32 mma.sync GEMMs (pre-rounded operands, 64x64 warp tiles, cp.async)
// + fused flash attention.
// ---------------------------------------------------------------------------

#define BB 8
#define NN_TOK 1024
#define DD 768
#define DEPTH 8
#define HEADS 12
#define DH 64
#define MLPD 3072
#define INNER 768
#define M_ROWS (BB * NN_TOK)          // 8192
#define QKV_LD (3 * INNER)            // 2304

// Scratch (device globals; allocation-free per harness rules)
__device__ float g_h[M_ROWS * DD];
__device__ float g_y[M_ROWS * DD];
__device__ float g_qkv[M_ROWS * QKV_LD];
__device__ float g_o[M_ROWS * INNER];
__device__ float g_mlp[M_ROWS * MLPD];
// tf32-rounded weight copies
__device__ float g_qw[DEPTH * DD * QKV_LD];
__device__ float g_ow[DEPTH * INNER * DD];
__device__ float g_w1[DEPTH * DD * MLPD];
__device__ float g_w2[DEPTH * MLPD * DD];

__device__ __forceinline__ float gelu_f(float x) {
    return 0.5f * x * (1.0f + erff(x * 0.70710678118654752f));
}
__device__ __forceinline__ float tf32f(float x) {
    unsigned u; asm("cvt.rna.tf32.f32 %0, %1;" : "=r"(u) : "f"(x));
    return __uint_as_float(u);
}
__device__ __forceinline__ void mma_tf32(float* d, const unsigned* a, const unsigned* b) {
    asm volatile(
        "mma.sync.aligned.m16n8k8.row.col.f32.tf32.tf32.f32 "
        "{%0,%1,%2,%3}, {%4,%5,%6,%7}, {%8,%9}, {%0,%1,%2,%3};\n"
        : "+f"(d[0]), "+f"(d[1]), "+f"(d[2]), "+f"(d[3])
        : "r"(a[0]), "r"(a[1]), "r"(a[2]), "r"(a[3]), "r"(b[0]), "r"(b[1]));
}
__device__ __forceinline__ void cp_async16(void* s, const void* g) {
    unsigned sa = (unsigned)__cvta_generic_to_shared(s);
    asm volatile("cp.async.cg.shared.global [%0], [%1], 16;\n" :: "r"(sa), "l"(g));
}
#define CP_COMMIT() asm volatile("cp.async.commit_group;\n" ::: "memory")
#define CP_WAIT(n)  asm volatile("cp.async.wait_group %0;\n" :: "n"(n) : "memory")

// ---------------------------------------------------------------------------
// tf32 pre-rounding prep (weights)
// ---------------------------------------------------------------------------
__global__ void round_tf32_kernel(const float* __restrict__ src,
                                  float* __restrict__ dst, int n4) {
    int i = blockIdx.x * 256 + threadIdx.x;
    if (i < n4) {
        float4 v = ((const float4*)src)[i];
        v.x = tf32f(v.x); v.y = tf32f(v.y); v.z = tf32f(v.z); v.w = tf32f(v.w);
        ((float4*)dst)[i] = v;
    }
}

// ---------------------------------------------------------------------------
// Patch embed
// ---------------------------------------------------------------------------
__global__ void patch_embed_kernel(const float* __restrict__ x,
                                   const float* __restrict__ wc,
                                   const float* __restrict__ bc,
                                   const float* __restrict__ pos,
                                   float* __restrict__ h) {
    int bn = blockIdx.x;
    int b = bn >> 10, n = bn & 1023;
    int py = n >> 5, px = n & 31;
    __shared__ float patch[192];
    int t = threadIdx.x;
    if (t < 192) {
        int c = t / 64, r = (t % 64) / 8, col = t % 8;
        patch[t] = x[(((size_t)b * 3 + c) * 256 + py * 8 + r) * 256 + px * 8 + col];
    }
    __syncthreads();
    for (int d = t; d < DD; d += 256) {
        float acc = bc[d];
        const float* wrow = wc + (size_t)d * 192;
        #pragma unroll 8
        for (int i = 0; i < 192; i++) acc += patch[i] * wrow[i];
        h[(size_t)bn * DD + d] = acc + pos[(size_t)n * DD + d];
    }
}

// ---------------------------------------------------------------------------
// LayerNorm (output rounded to tf32 — feeds GEMM A operand)
// ---------------------------------------------------------------------------
__global__ void ln_kernel(const float* __restrict__ x,
                          const float* __restrict__ w,
                          const float* __restrict__ b,
                          float* __restrict__ y) {
    int row = blockIdx.x;
    const float* xr = x + (size_t)row * DD;
    __shared__ float red[256];
    int t = threadIdx.x;
    float v0 = xr[t], v1 = xr[t + 256], v2 = xr[t + 512];
    red[t] = v0 + v1 + v2;
    __syncthreads();
    #pragma unroll
    for (int s = 128; s > 0; s >>= 1) { if (t < s) red[t] += red[t + s]; __syncthreads(); }
    float mean = red[0] * (1.0f / DD);
    __syncthreads();
    float d0 = v0 - mean, d1 = v1 - mean, d2 = v2 - mean;
    red[t] = d0 * d0 + d1 * d1 + d2 * d2;
    __syncthreads();
    #pragma unroll
    for (int s = 128; s > 0; s >>= 1) { if (t < s) red[t] += red[t + s]; __syncthreads(); }
    float rstd = rsqrtf(red[0] * (1.0f / DD) + 1e-5f);
    float* yr = y + (size_t)row * DD;
    yr[t]       = tf32f(d0 * rstd * w[t]       + b[t]);
    yr[t + 256] = tf32f(d1 * rstd * w[t + 256] + b[t + 256]);
    yr[t + 512] = tf32f(d2 * rstd * w[t + 512] + b[t + 512]);
}

// ---------------------------------------------------------------------------
// tf32 GEMM: C[M,N] = epi(A[M,K] @ W[K,N]). A and W pre-rounded to tf32.
// BM=BN=128, BK=16, 4-stage cp.async. 128 threads = 4 warps (2x2), warp tile
// 64x64 (4x8 grid of m16n8k8). As[stage][128][20], Bs[stage][16][136].
// ---------------------------------------------------------------------------
#define GSTAGES 4
#define GEMM_SMEM ((GSTAGES * 128 * 20 + GSTAGES * 16 * 136) * 4)

template <int BIAS, int GELU, int RES, int TF32OUT>
__global__ __launch_bounds__(128)
void mma_gemm(const float* __restrict__ A, const float* __restrict__ W,
              const float* __restrict__ bias, const float* __restrict__ res,
              float* __restrict__ C, int K, int N) {
    extern __shared__ float smem[];
    float (*As)[128][20] = (float(*)[128][20])smem;
    float (*Bs)[16][136] = (float(*)[16][136])(smem + GSTAGES * 128 * 20);

    int tid = threadIdx.x, wid = tid >> 5, lane = tid & 31;
    int g = lane >> 2, tg = lane & 3;
    int warp_m = (wid >> 1) * 64, warp_n = (wid & 1) * 64;
    int bm0 = blockIdx.y * 128, bn0 = blockIdx.x * 128;

    float acc[4][8][4];
    #pragma unroll
    for (int i = 0; i < 4; i++)
        #pragma unroll
        for (int j = 0; j < 8; j++)
            #pragma unroll
            for (int r = 0; r < 4; r++) acc[i][j][r] = 0.f;

    const float* Abase = A + (size_t)bm0 * K;
    const float* Wbase = W + bn0;

    int bk = tid >> 5, bn4 = tid & 31;          // B: 4 rows x 32 quads (x4)

    auto issue = [&](int tile, int s) {
        int k0 = tile * 16;
        const float* arow = Abase + (size_t)tid * K + k0;
        #pragma unroll
        for (int q = 0; q < 4; q++)
            cp_async16(&As[s][tid][q * 4], arow + q * 4);
        #pragma unroll
        for (int q = 0; q < 4; q++)
            cp_async16(&Bs[s][bk + q * 4][bn4 * 4],
                       Wbase + (size_t)(k0 + bk + q * 4) * N + bn4 * 4);
        CP_COMMIT();
    };

    int niter = K / 16;
    issue(0, 0); issue(1, 1); issue(2, 2);

    for (int i = 0; i < niter; i++) {
        int rem = niter - i;
        if (rem >= 3)      CP_WAIT(2);
        else if (rem == 2) CP_WAIT(1);
        else               CP_WAIT(0);
        __syncthreads();
        if (i + 3 < niter) issue(i + 3, (i + 3) & 3);
        int s = i & 3;
        #pragma unroll
        for (int ks = 0; ks < 2; ks++) {
            int k8 = ks * 8;
            unsigned bf[8][2];
            #pragma unroll
            for (int tj = 0; tj < 8; tj++) {
                int nb = warp_n + tj * 8 + g;
                bf[tj][0] = __float_as_uint(Bs[s][k8 + tg][nb]);
                bf[tj][1] = __float_as_uint(Bs[s][k8 + tg + 4][nb]);
            }
            #pragma unroll
            for (int ti = 0; ti < 4; ti++) {
                int mb = warp_m + ti * 16 + g;
                unsigned af[4];
                af[0] = __float_as_uint(As[s][mb][k8 + tg]);
                af[1] = __float_as_uint(As[s][mb + 8][k8 + tg]);
                af[2] = __float_as_uint(As[s][mb][k8 + tg + 4]);
                af[3] = __float_as_uint(As[s][mb + 8][k8 + tg + 4]);
                #pragma unroll
                for (int tj = 0; tj < 8; tj++)
                    mma_tf32(acc[ti][tj], af, bf[tj]);
            }
        }
    }

    #pragma unroll
    for (int ti = 0; ti < 4; ti++) {
        #pragma unroll
        for (int tj = 0; tj < 8; tj++) {
            int r0 = bm0 + warp_m + ti * 16 + g;
            int r1 = r0 + 8;
            int cc = bn0 + warp_n + tj * 8 + tg * 2;
            float v0 = acc[ti][tj][0], v1 = acc[ti][tj][1];
            float v2 = acc[ti][tj][2], v3 = acc[ti][tj][3];
            if (BIAS) {
                float b0 = bias[cc], b1 = bias[cc + 1];
                v0 += b0; v1 += b1; v2 += b0; v3 += b1;
            }
            if (GELU) {
                v0 = gelu_f(v0); v1 = gelu_f(v1);
                v2 = gelu_f(v2); v3 = gelu_f(v3);
            }
            if (RES) {
                const float* p0 = res + (size_t)r0 * N + cc;
                const float* p1 = res + (size_t)r1 * N + cc;
                v0 += p0[0]; v1 += p0[1]; v2 += p1[0]; v3 += p1[1];
            }
            if (TF32OUT) {
                v0 = tf32f(v0); v1 = tf32f(v1); v2 = tf32f(v2); v3 = tf32f(v3);
            }
            float2 o0 = {v0, v1}, o1 = {v2, v3};
            *(float2*)&C[(size_t)r0 * N + cc] = o0;
            *(float2*)&C[(size_t)r1 * N + cc] = o1;
        }
    }
}

// ---------------------------------------------------------------------------
// Fused flash attention. One block = one (b, head, 128-row Q tile).
// 8 warps x 16 Q rows. 16 KV tiles of 64. Online softmax. Inputs pre-rounded.
// ---------------------------------------------------------------------------
#define FLASH_SMEM ((128 * 68 + 64 * 68 + 64 * 72 + 128 * 68) * 4)

__global__ __launch_bounds__(256)
void flash_attn(const float* __restrict__ qkv, float* __restrict__ O) {
    extern __shared__ float fs[];
    float (*Qs)[68] = (float(*)[68])fs;
    float (*Ks)[68] = (float(*)[68])(fs + 128 * 68);
    float (*Vs)[72] = (float(*)[72])(fs + 128 * 68 + 64 * 68);
    float (*Ps)[68] = (float(*)[68])(fs + 128 * 68 + 64 * 68 + 64 * 72);

    int z = blockIdx.y, b = z / HEADS, hd = z % HEADS;
    const float* Qp = qkv + (size_t)b * NN_TOK * QKV_LD + hd * DH;
    const float* Kp = Qp + INNER;
    const float* Vp = Qp + 2 * INNER;
    int q0 = blockIdx.x * 128;

    int tid = threadIdx.x, wid = tid >> 5, lane = tid & 31;
    int g = lane >> 2, tg = lane & 3;
    int warp_m = wid * 16;

    int lr = tid >> 4, ld4 = tid & 15;

    auto issueK = [&](int j) {
        #pragma unroll
        for (int i = 0; i < 4; i++)
            cp_async16(&Ks[lr + i * 16][ld4 * 4],
                       Kp + (size_t)(j * 64 + lr + i * 16) * QKV_LD + ld4 * 4);
        CP_COMMIT();
    };
    auto issueV = [&](int j) {
        #pragma unroll
        for (int i = 0; i < 4; i++)
            cp_async16(&Vs[lr + i * 16][ld4 * 4],
                       Vp + (size_t)(j * 64 + lr + i * 16) * QKV_LD + ld4 * 4);
        CP_COMMIT();
    };

    #pragma unroll
    for (int i = 0; i < 8; i++)
        cp_async16(&Qs[lr + i * 16][ld4 * 4],
                   Qp + (size_t)(q0 + lr + i * 16) * QKV_LD + ld4 * 4);
    {
        #pragma unroll
        for (int i = 0; i < 4; i++)
            cp_async16(&Ks[lr + i * 16][ld4 * 4],
                       Kp + (size_t)(lr + i * 16) * QKV_LD + ld4 * 4);
        CP_COMMIT();
    }
    issueV(0);

    float m0 = -1e30f, m1 = -1e30f, l0 = 0.f, l1 = 0.f;
    float oa[8][4];
    #pragma unroll
    for (int tj = 0; tj < 8; tj++)
        #pragma unroll
        for (int r = 0; r < 4; r++) oa[tj][r] = 0.f;

    for (int j = 0; j < 16; j++) {
        CP_WAIT(1);
        __syncthreads();

        // S = Q @ K^T
        float sa[8][4];
        #pragma unroll
        for (int tj = 0; tj < 8; tj++)
            #pragma unroll
            for (int r = 0; r < 4; r++) sa[tj][r] = 0.f;
        #pragma unroll
        for (int k8 = 0; k8 < 64; k8 += 8) {
            unsigned af[4];
            af[0] = __float_as_uint(Qs[warp_m + g][k8 + tg]);
            af[1] = __float_as_uint(Qs[warp_m + g + 8][k8 + tg]);
            af[2] = __float_as_uint(Qs[warp_m + g][k8 + tg + 4]);
            af[3] = __float_as_uint(Qs[warp_m + g + 8][k8 + tg + 4]);
            #pragma unroll
            for (int tj = 0; tj < 8; tj++) {
                unsigned bf[2];
                bf[0] = __float_as_uint(Ks[tj * 8 + g][k8 + tg]);
                bf[1] = __float_as_uint(Ks[tj * 8 + g][k8 + tg + 4]);
                mma_tf32(sa[tj], af, bf);
            }
        }

        // Online softmax
        float mx0 = -1e30f, mx1 = -1e30f;
        #pragma unroll
        for (int tj = 0; tj < 8; tj++) {
            sa[tj][0] *= 0.125f; sa[tj][1] *= 0.125f;
            sa[tj][2] *= 0.125f; sa[tj][3] *= 0.125f;
            mx0 = fmaxf(mx0, fmaxf(sa[tj][0], sa[tj][1]));
            mx1 = fmaxf(mx1, fmaxf(sa[tj][2], sa[tj][3]));
        }
        mx0 = fmaxf(mx0, __shfl_xor_sync(0xffffffffu, mx0, 1));
        mx0 = fmaxf(mx0, __shfl_xor_sync(0xffffffffu, mx0, 2));
        mx1 = fmaxf(mx1, __shfl_xor_sync(0xffffffffu, mx1, 1));
        mx1 = fmaxf(mx1, __shfl_xor_sync(0xffffffffu, mx1, 2));
        float mn0 = fmaxf(m0, mx0), mn1 = fmaxf(m1, mx1);
        float a0 = __expf(m0 - mn0), a1 = __expf(m1 - mn1);
        float s0 = 0.f, s1 = 0.f;
        #pragma unroll
        for (int tj = 0; tj < 8; tj++) {
            float p0 = __expf(sa[tj][0] - mn0);
            float p1 = __expf(sa[tj][1] - mn0);
            float p2 = __expf(sa[tj][2] - mn1);
            float p3 = __expf(sa[tj][3] - mn1);
            s0 += p0 + p1; s1 += p2 + p3;
            Ps[warp_m + g][tj * 8 + 2 * tg]         = tf32f(p0);
            Ps[warp_m + g][tj * 8 + 2 * tg + 1]     = tf32f(p1);
            Ps[warp_m + g + 8][tj * 8 + 2 * tg]     = tf32f(p2);
            Ps[warp_m + g + 8][tj * 8 + 2 * tg + 1] = tf32f(p3);
            oa[tj][0] *= a0; oa[tj][1] *= a0;
            oa[tj][2] *= a1; oa[tj][3] *= a1;
        }
        s0 += __shfl_xor_sync(0xffffffffu, s0, 1);
        s0 += __shfl_xor_sync(0xffffffffu, s0, 2);
        s1 += __shfl_xor_sync(0xffffffffu, s1, 1);
        s1 += __shfl_xor_sync(0xffffffffu, s1, 2);
        l0 = l0 * a0 + s0; l1 = l1 * a1 + s1;
        m0 = mn0; m1 = mn1;

        __syncthreads();
        if (j < 15) issueK(j + 1);
        if (j < 15) { CP_WAIT(1); } else { CP_WAIT(0); }
        __syncthreads();

        // O += P @ V
        #pragma unroll
        for (int k8 = 0; k8 < 64; k8 += 8) {
            unsigned af[4];
            af[0] = __float_as_uint(Ps[warp_m + g][k8 + tg]);
            af[1] = __float_as_uint(Ps[warp_m + g + 8][k8 + tg]);
            af[2] = __float_as_uint(Ps[warp_m + g][k8 + tg + 4]);
            af[3] = __float_as_uint(Ps[warp_m + g + 8][k8 + tg + 4]);
            #pragma unroll
            for (int tj = 0; tj < 8; tj++) {
                unsigned bf[2];
                bf[0] = __float_as_uint(Vs[k8 + tg][tj * 8 + g]);
                bf[1] = __float_as_uint(Vs[k8 + tg + 4][tj * 8 + g]);
                mma_tf32(oa[tj], af, bf);
            }
        }
        __syncthreads();
        if (j < 15) issueV(j + 1);
    }

    // Normalize, round to tf32 (feeds out-proj GEMM), write O
    float i0 = 1.f / l0, i1 = 1.f / l1;
    int r0 = q0 + warp_m + g, r1 = r0 + 8;
    float* Ob = O + (size_t)b * NN_TOK * INNER + hd * DH;
    #pragma unroll
    for (int tj = 0; tj < 8; tj++) {
        int cc = tj * 8 + 2 * tg;
        float2 v0 = {tf32f(oa[tj][0] * i0), tf32f(oa[tj][1] * i0)};
        float2 v1 = {tf32f(oa[tj][2] * i1), tf32f(oa[tj][3] * i1)};
        *(float2*)&Ob[(size_t)r0 * INNER + cc] = v0;
        *(float2*)&Ob[(size_t)r1 * INNER + cc] = v1;
    }
}

// ---------------------------------------------------------------------------
extern "C" void kernel_launch(void* const* d_in, const int* in_sizes, int n_in,
                              void* d_out, int out_size) {
    const float* x      = (const float*)d_in[0];
    const float* w_conv = (const float*)d_in[1];
    const float* b_conv = (const float*)d_in[2];
    const float* pos    = (const float*)d_in[3];
    const float* ln1_w  = (const float*)d_in[4];
    const float* ln1_b  = (const float*)d_in[5];
    const float* qkv_w  = (const float*)d_in[6];
    const float* out_w  = (const float*)d_in[7];
    const float* out_b  = (const float*)d_in[8];
    const float* ln2_w  = (const float*)d_in[9];
    const float* ln2_b  = (const float*)d_in[10];
    const float* w1     = (const float*)d_in[11];
    const float* b1     = (const float*)d_in[12];
    const float* w2     = (const float*)d_in[13];
    const float* b2     = (const float*)d_in[14];

    float *h, *y, *qkv, *o, *mlp, *qw, *ow, *W1p, *W2p;
    cudaGetSymbolAddress((void**)&h,   g_h);
    cudaGetSymbolAddress((void**)&y,   g_y);
    cudaGetSymbolAddress((void**)&qkv, g_qkv);
    cudaGetSymbolAddress((void**)&o,   g_o);
    cudaGetSymbolAddress((void**)&mlp, g_mlp);
    cudaGetSymbolAddress((void**)&qw,  g_qw);
    cudaGetSymbolAddress((void**)&ow,  g_ow);
    cudaGetSymbolAddress((void**)&W1p, g_w1);
    cudaGetSymbolAddress((void**)&W2p, g_w2);

    cudaFuncSetAttribute(mma_gemm<0,0,0,1>, cudaFuncAttributeMaxDynamicSharedMemorySize, GEMM_SMEM);
    cudaFuncSetAttribute(mma_gemm<1,0,1,0>, cudaFuncAttributeMaxDynamicSharedMemorySize, GEMM_SMEM);
    cudaFuncSetAttribute(mma_gemm<1,1,0,1>, cudaFuncAttributeMaxDynamicSharedMemorySize, GEMM_SMEM);
    cudaFuncSetAttribute(flash_attn,        cudaFuncAttributeMaxDynamicSharedMemorySize, FLASH_SMEM);

    // Pre-round all weights to tf32 (removes cvt from GEMM inner loops)
    {
        int n;
        n = DEPTH * DD * QKV_LD / 4;
        round_tf32_kernel<<<(n + 255) / 256, 256>>>(qkv_w, qw, n);
        n = DEPTH * INNER * DD / 4;
        round_tf32_kernel<<<(n + 255) / 256, 256>>>(out_w, ow, n);
        n = DEPTH * DD * MLPD / 4;
        round_tf32_kernel<<<(n + 255) / 256, 256>>>(w1, W1p, n);
        n = DEPTH * MLPD * DD / 4;
        round_tf32_kernel<<<(n + 255) / 256, 256>>>(w2, W2p, n);
    }

    patch_embed_kernel<<<M_ROWS, 256>>>(x, w_conv, b_conv, pos, h);

    for (int l = 0; l < DEPTH; l++) {
        const float* l1w = ln1_w + (size_t)l * DD;
        const float* l1b = ln1_b + (size_t)l * DD;
        const float* qwl = qw + (size_t)l * DD * QKV_LD;
        const float* owl = ow + (size_t)l * INNER * DD;
        const float* ob  = out_b + (size_t)l * DD;
        const float* l2w = ln2_w + (size_t)l * DD;
        const float* l2b = ln2_b + (size_t)l * DD;
        const float* W1l = W1p + (size_t)l * DD * MLPD;
        const float* B1  = b1 + (size_t)l * MLPD;
        const float* W2l = W2p + (size_t)l * MLPD * DD;
        const float* B2  = b2 + (size_t)l * DD;

        // PreNorm + QKV projection (tf32-rounded output feeds attention)
        ln_kernel<<<M_ROWS, 256>>>(h, l1w, l1b, y);
        mma_gemm<0,0,0,1><<<dim3(QKV_LD / 128, M_ROWS / 128), 128, GEMM_SMEM>>>(
            y, qwl, nullptr, nullptr, qkv, DD, QKV_LD);

        // Fused flash attention
        flash_attn<<<dim3(NN_TOK / 128, BB * HEADS), 256, FLASH_SMEM>>>(qkv, o);

        // Output projection + residual
        mma_gemm<1,0,1,0><<<dim3(DD / 128, M_ROWS / 128), 128, GEMM_SMEM>>>(
            o, owl, ob, h, h, INNER, DD);

        // PreNorm + FFN
        ln_kernel<<<M_ROWS, 256>>>(h, l2w, l2b, y);
        mma_gemm<1,1,0,1><<<dim3(MLPD / 128, M_ROWS / 128), 128, GEMM_SMEM>>>(
            y, W1l, B1, nullptr, mlp, DD, MLPD);
        float* cdst = (l == DEPTH - 1) ? (float*)d_out : h;
        mma_gemm<1,0,1,0><<<dim3(DD / 128, M_ROWS / 128), 128, GEMM_SMEM>>>(
            mlp, W2l, B2, h, cdst, MLPD, DD);
    }
}

// round 8
// speedup vs baseline: 1.0817x; 1.0817x over previous
#include <cuda_runtime.h>
#include <cuda_bf16.h>
#include <math.h>

// ---------------------------------------------------------------------------
// ViT encoder: B=8, N=1024 tokens, D=768, 8 layers, 12 heads x 64, MLP 3072.
// tf32 mma.sync GEMMs (pre-rounded operands, 8 warps, 64x32 warp tiles,
// 4-stage cp.async) + fused flash attention.
// ---------------------------------------------------------------------------

#define BB 8
#define NN_TOK 1024
#define DD 768
#define DEPTH 8
#define HEADS 12
#define DH 64
#define MLPD 3072
#define INNER 768
#define M_ROWS (BB * NN_TOK)          // 8192
#define QKV_LD (3 * INNER)            // 2304

// Scratch (device globals; allocation-free per harness rules)
__device__ float g_h[M_ROWS * DD];
__device__ float g_y[M_ROWS * DD];
__device__ float g_qkv[M_ROWS * QKV_LD];
__device__ float g_o[M_ROWS * INNER];
__device__ float g_mlp[M_ROWS * MLPD];
// tf32-rounded weight copies
__device__ float g_qw[DEPTH * DD * QKV_LD];
__device__ float g_ow[DEPTH * INNER * DD];
__device__ float g_w1[DEPTH * DD * MLPD];
__device__ float g_w2[DEPTH * MLPD * DD];

__device__ __forceinline__ float gelu_f(float x) {
    return 0.5f * x * (1.0f + erff(x * 0.70710678118654752f));
}
__device__ __forceinline__ float tf32f(float x) {
    unsigned u; asm("cvt.rna.tf32.f32 %0, %1;" : "=r"(u) : "f"(x));
    return __uint_as_float(u);
}
__device__ __forceinline__ void mma_tf32(float* d, const unsigned* a, const unsigned* b) {
    asm volatile(
        "mma.sync.aligned.m16n8k8.row.col.f32.tf32.tf32.f32 "
        "{%0,%1,%2,%3}, {%4,%5,%6,%7}, {%8,%9}, {%0,%1,%2,%3};\n"
        : "+f"(d[0]), "+f"(d[1]), "+f"(d[2]), "+f"(d[3])
        : "r"(a[0]), "r"(a[1]), "r"(a[2]), "r"(a[3]), "r"(b[0]), "r"(b[1]));
}
__device__ __forceinline__ void cp_async16(void* s, const void* g) {
    unsigned sa = (unsigned)__cvta_generic_to_shared(s);
    asm volatile("cp.async.cg.shared.global [%0], [%1], 16;\n" :: "r"(sa), "l"(g));
}
#define CP_COMMIT() asm volatile("cp.async.commit_group;\n" ::: "memory")
#define CP_WAIT(n)  asm volatile("cp.async.wait_group %0;\n" :: "n"(n) : "memory")

// ---------------------------------------------------------------------------
// tf32 pre-rounding prep (weights)
// ---------------------------------------------------------------------------
__global__ void round_tf32_kernel(const float* __restrict__ src,
                                  float* __restrict__ dst, int n4) {
    int i = blockIdx.x * 256 + threadIdx.x;
    if (i < n4) {
        float4 v = ((const float4*)src)[i];
        v.x = tf32f(v.x); v.y = tf32f(v.y); v.z = tf32f(v.z); v.w = tf32f(v.w);
        ((float4*)dst)[i] = v;
    }
}

// ---------------------------------------------------------------------------
// Patch embed
// ---------------------------------------------------------------------------
__global__ void patch_embed_kernel(const float* __restrict__ x,
                                   const float* __restrict__ wc,
                                   const float* __restrict__ bc,
                                   const float* __restrict__ pos,
                                   float* __restrict__ h) {
    int bn = blockIdx.x;
    int b = bn >> 10, n = bn & 1023;
    int py = n >> 5, px = n & 31;
    __shared__ float patch[192];
    int t = threadIdx.x;
    if (t < 192) {
        int c = t / 64, r = (t % 64) / 8, col = t % 8;
        patch[t] = x[(((size_t)b * 3 + c) * 256 + py * 8 + r) * 256 + px * 8 + col];
    }
    __syncthreads();
    for (int d = t; d < DD; d += 256) {
        float acc = bc[d];
        const float* wrow = wc + (size_t)d * 192;
        #pragma unroll 8
        for (int i = 0; i < 192; i++) acc += patch[i] * wrow[i];
        h[(size_t)bn * DD + d] = acc + pos[(size_t)n * DD + d];
    }
}

// ---------------------------------------------------------------------------
// LayerNorm (output rounded to tf32 — feeds GEMM A operand)
// ---------------------------------------------------------------------------
__global__ void ln_kernel(const float* __restrict__ x,
                          const float* __restrict__ w,
                          const float* __restrict__ b,
                          float* __restrict__ y) {
    int row = blockIdx.x;
    const float* xr = x + (size_t)row * DD;
    __shared__ float red[256];
    int t = threadIdx.x;
    float v0 = xr[t], v1 = xr[t + 256], v2 = xr[t + 512];
    red[t] = v0 + v1 + v2;
    __syncthreads();
    #pragma unroll
    for (int s = 128; s > 0; s >>= 1) { if (t < s) red[t] += red[t + s]; __syncthreads(); }
    float mean = red[0] * (1.0f / DD);
    __syncthreads();
    float d0 = v0 - mean, d1 = v1 - mean, d2 = v2 - mean;
    red[t] = d0 * d0 + d1 * d1 + d2 * d2;
    __syncthreads();
    #pragma unroll
    for (int s = 128; s > 0; s >>= 1) { if (t < s) red[t] += red[t + s]; __syncthreads(); }
    float rstd = rsqrtf(red[0] * (1.0f / DD) + 1e-5f);
    float* yr = y + (size_t)row * DD;
    yr[t]       = tf32f(d0 * rstd * w[t]       + b[t]);
    yr[t + 256] = tf32f(d1 * rstd * w[t + 256] + b[t + 256]);
    yr[t + 512] = tf32f(d2 * rstd * w[t + 512] + b[t + 512]);
}

// ---------------------------------------------------------------------------
// tf32 GEMM: C[M,N] = epi(A[M,K] @ W[K,N]). Operands pre-rounded to tf32.
// BM=BN=128, BK=16, 4-stage cp.async. 256 threads = 8 warps (2x4),
// warp tile 64x32 (4x4 grid of m16n8k8). As[stage][128][20], Bs[stage][16][136].
// ---------------------------------------------------------------------------
#define GSTAGES 4
#define GEMM_SMEM ((GSTAGES * 128 * 20 + GSTAGES * 16 * 136) * 4)

template <int BIAS, int GELU, int RES, int TF32OUT>
__global__ __launch_bounds__(256)
void mma_gemm(const float* __restrict__ A, const float* __restrict__ W,
              const float* __restrict__ bias, const float* __restrict__ res,
              float* __restrict__ C, int K, int N) {
    extern __shared__ float smem[];
    float (*As)[128][20] = (float(*)[128][20])smem;
    float (*Bs)[16][136] = (float(*)[16][136])(smem + GSTAGES * 128 * 20);

    int tid = threadIdx.x, wid = tid >> 5, lane = tid & 31;
    int g = lane >> 2, tg = lane & 3;
    int warp_m = (wid >> 2) * 64, warp_n = (wid & 3) * 32;
    int bm0 = blockIdx.y * 128, bn0 = blockIdx.x * 128;

    float acc[4][4][4];
    #pragma unroll
    for (int i = 0; i < 4; i++)
        #pragma unroll
        for (int j = 0; j < 4; j++)
            #pragma unroll
            for (int r = 0; r < 4; r++) acc[i][j][r] = 0.f;

    const float* Abase = A + (size_t)bm0 * K;
    const float* Wbase = W + bn0;

    int am = tid >> 2, ak4 = tid & 3;          // A: 64 rows x 4 quads (x2)
    int bk = tid >> 5, bn4 = tid & 31;         // B: 8 rows x 32 quads (x2)

    auto issue = [&](int tile, int s) {
        int k0 = tile * 16;
        cp_async16(&As[s][am][ak4 * 4],       Abase + (size_t)am * K + k0 + ak4 * 4);
        cp_async16(&As[s][am + 64][ak4 * 4],  Abase + (size_t)(am + 64) * K + k0 + ak4 * 4);
        cp_async16(&Bs[s][bk][bn4 * 4],       Wbase + (size_t)(k0 + bk) * N + bn4 * 4);
        cp_async16(&Bs[s][bk + 8][bn4 * 4],   Wbase + (size_t)(k0 + bk + 8) * N + bn4 * 4);
        CP_COMMIT();
    };

    int niter = K / 16;
    issue(0, 0); issue(1, 1); issue(2, 2);

    for (int i = 0; i < niter; i++) {
        int rem = niter - i;
        if (rem >= 3)      CP_WAIT(2);
        else if (rem == 2) CP_WAIT(1);
        else               CP_WAIT(0);
        __syncthreads();
        if (i + 3 < niter) issue(i + 3, (i + 3) & 3);
        int s = i & 3;
        #pragma unroll
        for (int ks = 0; ks < 2; ks++) {
            int k8 = ks * 8;
            unsigned bf[4][2];
            #pragma unroll
            for (int tj = 0; tj < 4; tj++) {
                int nb = warp_n + tj * 8 + g;
                bf[tj][0] = __float_as_uint(Bs[s][k8 + tg][nb]);
                bf[tj][1] = __float_as_uint(Bs[s][k8 + tg + 4][nb]);
            }
            #pragma unroll
            for (int ti = 0; ti < 4; ti++) {
                int mb = warp_m + ti * 16 + g;
                unsigned af[4];
                af[0] = __float_as_uint(As[s][mb][k8 + tg]);
                af[1] = __float_as_uint(As[s][mb + 8][k8 + tg]);
                af[2] = __float_as_uint(As[s][mb][k8 + tg + 4]);
                af[3] = __float_as_uint(As[s][mb + 8][k8 + tg + 4]);
                #pragma unroll
                for (int tj = 0; tj < 4; tj++)
                    mma_tf32(acc[ti][tj], af, bf[tj]);
            }
        }
    }

    #pragma unroll
    for (int ti = 0; ti < 4; ti++) {
        #pragma unroll
        for (int tj = 0; tj < 4; tj++) {
            int r0 = bm0 + warp_m + ti * 16 + g;
            int r1 = r0 + 8;
            int cc = bn0 + warp_n + tj * 8 + tg * 2;
            float v0 = acc[ti][tj][0], v1 = acc[ti][tj][1];
            float v2 = acc[ti][tj][2], v3 = acc[ti][tj][3];
            if (BIAS) {
                float b0 = bias[cc], b1 = bias[cc + 1];
                v0 += b0; v1 += b1; v2 += b0; v3 += b1;
            }
            if (GELU) {
                v0 = gelu_f(v0); v1 = gelu_f(v1);
                v2 = gelu_f(v2); v3 = gelu_f(v3);
            }
            if (RES) {
                const float* p0 = res + (size_t)r0 * N + cc;
                const float* p1 = res + (size_t)r1 * N + cc;
                v0 += p0[0]; v1 += p0[1]; v2 += p1[0]; v3 += p1[1];
            }
            if (TF32OUT) {
                v0 = tf32f(v0); v1 = tf32f(v1); v2 = tf32f(v2); v3 = tf32f(v3);
            }
            float2 o0 = {v0, v1}, o1 = {v2, v3};
            *(float2*)&C[(size_t)r0 * N + cc] = o0;
            *(float2*)&C[(size_t)r1 * N + cc] = o1;
        }
    }
}

// ---------------------------------------------------------------------------
// Fused flash attention. One block = one (b, head, 128-row Q tile).
// 8 warps x 16 Q rows. 16 KV tiles of 64. Online softmax. Inputs pre-rounded.
// ---------------------------------------------------------------------------
#define FLASH_SMEM ((128 * 68 + 64 * 68 + 64 * 72 + 128 * 68) * 4)

__global__ __launch_bounds__(256)
void flash_attn(const float* __restrict__ qkv, float* __restrict__ O) {
    extern __shared__ float fs[];
    float (*Qs)[68] = (float(*)[68])fs;
    float (*Ks)[68] = (float(*)[68])(fs + 128 * 68);
    float (*Vs)[72] = (float(*)[72])(fs + 128 * 68 + 64 * 68);
    float (*Ps)[68] = (float(*)[68])(fs + 128 * 68 + 64 * 68 + 64 * 72);

    int z = blockIdx.y, b = z / HEADS, hd = z % HEADS;
    const float* Qp = qkv + (size_t)b * NN_TOK * QKV_LD + hd * DH;
    const float* Kp = Qp + INNER;
    const float* Vp = Qp + 2 * INNER;
    int q0 = blockIdx.x * 128;

    int tid = threadIdx.x, wid = tid >> 5, lane = tid & 31;
    int g = lane >> 2, tg = lane & 3;
    int warp_m = wid * 16;

    int lr = tid >> 4, ld4 = tid & 15;

    auto issueK = [&](int j) {
        #pragma unroll
        for (int i = 0; i < 4; i++)
            cp_async16(&Ks[lr + i * 16][ld4 * 4],
                       Kp + (size_t)(j * 64 + lr + i * 16) * QKV_LD + ld4 * 4);
        CP_COMMIT();
    };
    auto issueV = [&](int j) {
        #pragma unroll
        for (int i = 0; i < 4; i++)
            cp_async16(&Vs[lr + i * 16][ld4 * 4],
                       Vp + (size_t)(j * 64 + lr + i * 16) * QKV_LD + ld4 * 4);
        CP_COMMIT();
    };

    #pragma unroll
    for (int i = 0; i < 8; i++)
        cp_async16(&Qs[lr + i * 16][ld4 * 4],
                   Qp + (size_t)(q0 + lr + i * 16) * QKV_LD + ld4 * 4);
    {
        #pragma unroll
        for (int i = 0; i < 4; i++)
            cp_async16(&Ks[lr + i * 16][ld4 * 4],
                       Kp + (size_t)(lr + i * 16) * QKV_LD + ld4 * 4);
        CP_COMMIT();
    }
    issueV(0);

    float m0 = -1e30f, m1 = -1e30f, l0 = 0.f, l1 = 0.f;
    float oa[8][4];
    #pragma unroll
    for (int tj = 0; tj < 8; tj++)
        #pragma unroll
        for (int r = 0; r < 4; r++) oa[tj][r] = 0.f;

    for (int j = 0; j < 16; j++) {
        CP_WAIT(1);
        __syncthreads();

        // S = Q @ K^T
        float sa[8][4];
        #pragma unroll
        for (int tj = 0; tj < 8; tj++)
            #pragma unroll
            for (int r = 0; r < 4; r++) sa[tj][r] = 0.f;
        #pragma unroll
        for (int k8 = 0; k8 < 64; k8 += 8) {
            unsigned af[4];
            af[0] = __float_as_uint(Qs[warp_m + g][k8 + tg]);
            af[1] = __float_as_uint(Qs[warp_m + g + 8][k8 + tg]);
            af[2] = __float_as_uint(Qs[warp_m + g][k8 + tg + 4]);
            af[3] = __float_as_uint(Qs[warp_m + g + 8][k8 + tg + 4]);
            #pragma unroll
            for (int tj = 0; tj < 8; tj++) {
                unsigned bf[2];
                bf[0] = __float_as_uint(Ks[tj * 8 + g][k8 + tg]);
                bf[1] = __float_as_uint(Ks[tj * 8 + g][k8 + tg + 4]);
                mma_tf32(sa[tj], af, bf);
            }
        }

        // Online softmax
        float mx0 = -1e30f, mx1 = -1e30f;
        #pragma unroll
        for (int tj = 0; tj < 8; tj++) {
            sa[tj][0] *= 0.125f; sa[tj][1] *= 0.125f;
            sa[tj][2] *= 0.125f; sa[tj][3] *= 0.125f;
            mx0 = fmaxf(mx0, fmaxf(sa[tj][0], sa[tj][1]));
            mx1 = fmaxf(mx1, fmaxf(sa[tj][2], sa[tj][3]));
        }
        mx0 = fmaxf(mx0, __shfl_xor_sync(0xffffffffu, mx0, 1));
        mx0 = fmaxf(mx0, __shfl_xor_sync(0xffffffffu, mx0, 2));
        mx1 = fmaxf(mx1, __shfl_xor_sync(0xffffffffu, mx1, 1));
        mx1 = fmaxf(mx1, __shfl_xor_sync(0xffffffffu, mx1, 2));
        float mn0 = fmaxf(m0, mx0), mn1 = fmaxf(m1, mx1);
        float a0 = __expf(m0 - mn0), a1 = __expf(m1 - mn1);
        float s0 = 0.f, s1 = 0.f;
        #pragma unroll
        for (int tj = 0; tj < 8; tj++) {
            float p0 = __expf(sa[tj][0] - mn0);
            float p1 = __expf(sa[tj][1] - mn0);
            float p2 = __expf(sa[tj][2] - mn1);
            float p3 = __expf(sa[tj][3] - mn1);
            s0 += p0 + p1; s1 += p2 + p3;
            Ps[warp_m + g][tj * 8 + 2 * tg]         = tf32f(p0);
            Ps[warp_m + g][tj * 8 + 2 * tg + 1]     = tf32f(p1);
            Ps[warp_m + g + 8][tj * 8 + 2 * tg]     = tf32f(p2);
            Ps[warp_m + g + 8][tj * 8 + 2 * tg + 1] = tf32f(p3);
            oa[tj][0] *= a0; oa[tj][1] *= a0;
            oa[tj][2] *= a1; oa[tj][3] *= a1;
        }
        s0 += __shfl_xor_sync(0xffffffffu, s0, 1);
        s0 += __shfl_xor_sync(0xffffffffu, s0, 2);
        s1 += __shfl_xor_sync(0xffffffffu, s1, 1);
        s1 += __shfl_xor_sync(0xffffffffu, s1, 2);
        l0 = l0 * a0 + s0; l1 = l1 * a1 + s1;
        m0 = mn0; m1 = mn1;

        __syncthreads();
        if (j < 15) issueK(j + 1);
        if (j < 15) { CP_WAIT(1); } else { CP_WAIT(0); }
        __syncthreads();

        // O += P @ V
        #pragma unroll
        for (int k8 = 0; k8 < 64; k8 += 8) {
            unsigned af[4];
            af[0] = __float_as_uint(Ps[warp_m + g][k8 + tg]);
            af[1] = __float_as_uint(Ps[warp_m + g + 8][k8 + tg]);
            af[2] = __float_as_uint(Ps[warp_m + g][k8 + tg + 4]);
            af[3] = __float_as_uint(Ps[warp_m + g + 8][k8 + tg + 4]);
            #pragma unroll
            for (int tj = 0; tj < 8; tj++) {
                unsigned bf[2];
                bf[0] = __float_as_uint(Vs[k8 + tg][tj * 8 + g]);
                bf[1] = __float_as_uint(Vs[k8 + tg + 4][tj * 8 + g]);
                mma_tf32(oa[tj], af, bf);
            }
        }
        __syncthreads();
        if (j < 15) issueV(j + 1);
    }

    // Normalize, round to tf32 (feeds out-proj GEMM), write O
    float i0 = 1.f / l0, i1 = 1.f / l1;
    int r0 = q0 + warp_m + g, r1 = r0 + 8;
    float* Ob = O + (size_t)b * NN_TOK * INNER + hd * DH;
    #pragma unroll
    for (int tj = 0; tj < 8; tj++) {
        int cc = tj * 8 + 2 * tg;
        float2 v0 = {tf32f(oa[tj][0] * i0), tf32f(oa[tj][1] * i0)};
        float2 v1 = {tf32f(oa[tj][2] * i1), tf32f(oa[tj][3] * i1)};
        *(float2*)&Ob[(size_t)r0 * INNER + cc] = v0;
        *(float2*)&Ob[(size_t)r1 * INNER + cc] = v1;
    }
}

// ---------------------------------------------------------------------------
extern "C" void kernel_launch(void* const* d_in, const int* in_sizes, int n_in,
                              void* d_out, int out_size) {
    const float* x      = (const float*)d_in[0];
    const float* w_conv = (const float*)d_in[1];
    const float* b_conv = (const float*)d_in[2];
    const float* pos    = (const float*)d_in[3];
    const float* ln1_w  = (const float*)d_in[4];
    const float* ln1_b  = (const float*)d_in[5];
    const float* qkv_w  = (const float*)d_in[6];
    const float* out_w  = (const float*)d_in[7];
    const float* out_b  = (const float*)d_in[8];
    const float* ln2_w  = (const float*)d_in[9];
    const float* ln2_b  = (const float*)d_in[10];
    const float* w1     = (const float*)d_in[11];
    const float* b1     = (const float*)d_in[12];
    const float* w2     = (const float*)d_in[13];
    const float* b2     = (const float*)d_in[14];

    float *h, *y, *qkv, *o, *mlp, *qw, *ow, *W1p, *W2p;
    cudaGetSymbolAddress((void**)&h,   g_h);
    cudaGetSymbolAddress((void**)&y,   g_y);
    cudaGetSymbolAddress((void**)&qkv, g_qkv);
    cudaGetSymbolAddress((void**)&o,   g_o);
    cudaGetSymbolAddress((void**)&mlp, g_mlp);
    cudaGetSymbolAddress((void**)&qw,  g_qw);
    cudaGetSymbolAddress((void**)&ow,  g_ow);
    cudaGetSymbolAddress((void**)&W1p, g_w1);
    cudaGetSymbolAddress((void**)&W2p, g_w2);

    cudaFuncSetAttribute(mma_gemm<0,0,0,1>, cudaFuncAttributeMaxDynamicSharedMemorySize, GEMM_SMEM);
    cudaFuncSetAttribute(mma_gemm<1,0,1,0>, cudaFuncAttributeMaxDynamicSharedMemorySize, GEMM_SMEM);
    cudaFuncSetAttribute(mma_gemm<1,1,0,1>, cudaFuncAttributeMaxDynamicSharedMemorySize, GEMM_SMEM);
    cudaFuncSetAttribute(flash_attn,        cudaFuncAttributeMaxDynamicSharedMemorySize, FLASH_SMEM);

    // Pre-round all weights to tf32 (removes cvt from GEMM inner loops)
    {
        int n;
        n = DEPTH * DD * QKV_LD / 4;
        round_tf32_kernel<<<(n + 255) / 256, 256>>>(qkv_w, qw, n);
        n = DEPTH * INNER * DD / 4;
        round_tf32_kernel<<<(n + 255) / 256, 256>>>(out_w, ow, n);
        n = DEPTH * DD * MLPD / 4;
        round_tf32_kernel<<<(n + 255) / 256, 256>>>(w1, W1p, n);
        n = DEPTH * MLPD * DD / 4;
        round_tf32_kernel<<<(n + 255) / 256, 256>>>(w2, W2p, n);
    }

    patch_embed_kernel<<<M_ROWS, 256>>>(x, w_conv, b_conv, pos, h);

    for (int l = 0; l < DEPTH; l++) {
        const float* l1w = ln1_w + (size_t)l * DD;
        const float* l1b = ln1_b + (size_t)l * DD;
        const float* qwl = qw + (size_t)l * DD * QKV_LD;
        const float* owl = ow + (size_t)l * INNER * DD;
        const float* ob  = out_b + (size_t)l * DD;
        const float* l2w = ln2_w + (size_t)l * DD;
        const float* l2b = ln2_b + (size_t)l * DD;
        const float* W1l = W1p + (size_t)l * DD * MLPD;
        const float* B1  = b1 + (size_t)l * MLPD;
        const float* W2l = W2p + (size_t)l * MLPD * DD;
        const float* B2  = b2 + (size_t)l * DD;

        // PreNorm + QKV projection (tf32-rounded output feeds attention)
        ln_kernel<<<M_ROWS, 256>>>(h, l1w, l1b, y);
        mma_gemm<0,0,0,1><<<dim3(QKV_LD / 128, M_ROWS / 128), 256, GEMM_SMEM>>>(
            y, qwl, nullptr, nullptr, qkv, DD, QKV_LD);

        // Fused flash attention
        flash_attn<<<dim3(NN_TOK / 128, BB * HEADS), 256, FLASH_SMEM>>>(qkv, o);

        // Output projection + residual
        mma_gemm<1,0,1,0><<<dim3(DD / 128, M_ROWS / 128), 256, GEMM_SMEM>>>(
            o, owl, ob, h, h, INNER, DD);

        // PreNorm + FFN
        ln_kernel<<<M_ROWS, 256>>>(h, l2w, l2b, y);
        mma_gemm<1,1,0,1><<<dim3(MLPD / 128, M_ROWS / 128), 256, GEMM_SMEM>>>(
            y, W1l, B1, nullptr, mlp, DD, MLPD);
        float* cdst = (l == DEPTH - 1) ? (float*)d_out : h;
        mma_gemm<1,0,1,0><<<dim3(DD / 128, M_ROWS / 128), 256, GEMM_SMEM>>>(
            mlp, W2l, B2, h, cdst, MLPD, DD);
    }
}

// round 10
// speedup vs baseline: 1.1178x; 1.0333x over previous
#include <cuda_runtime.h>
#include <cuda_bf16.h>
#include <math.h>

// ---------------------------------------------------------------------------
// ViT encoder: B=8, N=1024 tokens, D=768, 8 layers, 12 heads x 64, MLP 3072.
// tf32 mma.sync GEMMs (pre-rounded operands, 8 warps, 64x32 warp tiles,
// 4-stage cp.async) + fused flash attention. 2 blocks/SM via carveout hint.
// ---------------------------------------------------------------------------

#define BB 8
#define NN_TOK 1024
#define DD 768
#define DEPTH 8
#define HEADS 12
#define DH 64
#define MLPD 3072
#define INNER 768
#define M_ROWS (BB * NN_TOK)          // 8192
#define QKV_LD (3 * INNER)            // 2304

// Scratch (device globals; allocation-free per harness rules)
__device__ float g_h[M_ROWS * DD];
__device__ float g_y[M_ROWS * DD];
__device__ float g_qkv[M_ROWS * QKV_LD];
__device__ float g_o[M_ROWS * INNER];
__device__ float g_mlp[M_ROWS * MLPD];
// tf32-rounded weight copies
__device__ float g_qw[DEPTH * DD * QKV_LD];
__device__ float g_ow[DEPTH * INNER * DD];
__device__ float g_w1[DEPTH * DD * MLPD];
__device__ float g_w2[DEPTH * MLPD * DD];

__device__ __forceinline__ float gelu_f(float x) {
    return 0.5f * x * (1.0f + erff(x * 0.70710678118654752f));
}
__device__ __forceinline__ float tf32f(float x) {
    unsigned u; asm("cvt.rna.tf32.f32 %0, %1;" : "=r"(u) : "f"(x));
    return __uint_as_float(u);
}
__device__ __forceinline__ void mma_tf32(float* d, const unsigned* a, const unsigned* b) {
    asm volatile(
        "mma.sync.aligned.m16n8k8.row.col.f32.tf32.tf32.f32 "
        "{%0,%1,%2,%3}, {%4,%5,%6,%7}, {%8,%9}, {%0,%1,%2,%3};\n"
        : "+f"(d[0]), "+f"(d[1]), "+f"(d[2]), "+f"(d[3])
        : "r"(a[0]), "r"(a[1]), "r"(a[2]), "r"(a[3]), "r"(b[0]), "r"(b[1]));
}
__device__ __forceinline__ void cp_async16(void* s, const void* g) {
    unsigned sa = (unsigned)__cvta_generic_to_shared(s);
    asm volatile("cp.async.cg.shared.global [%0], [%1], 16;\n" :: "r"(sa), "l"(g));
}
#define CP_COMMIT() asm volatile("cp.async.commit_group;\n" ::: "memory")
#define CP_WAIT(n)  asm volatile("cp.async.wait_group %0;\n" :: "n"(n) : "memory")

// ---------------------------------------------------------------------------
// tf32 pre-rounding prep (weights)
// ---------------------------------------------------------------------------
__global__ void round_tf32_kernel(const float* __restrict__ src,
                                  float* __restrict__ dst, int n4) {
    int i = blockIdx.x * 256 + threadIdx.x;
    if (i < n4) {
        float4 v = ((const float4*)src)[i];
        v.x = tf32f(v.x); v.y = tf32f(v.y); v.z = tf32f(v.z); v.w = tf32f(v.w);
        ((float4*)dst)[i] = v;
    }
}

// ---------------------------------------------------------------------------
// Patch embed
// ---------------------------------------------------------------------------
__global__ void patch_embed_kernel(const float* __restrict__ x,
                                   const float* __restrict__ wc,
                                   const float* __restrict__ bc,
                                   const float* __restrict__ pos,
                                   float* __restrict__ h) {
    int bn = blockIdx.x;
    int b = bn >> 10, n = bn & 1023;
    int py = n >> 5, px = n & 31;
    __shared__ float patch[192];
    int t = threadIdx.x;
    if (t < 192) {
        int c = t / 64, r = (t % 64) / 8, col = t % 8;
        patch[t] = x[(((size_t)b * 3 + c) * 256 + py * 8 + r) * 256 + px * 8 + col];
    }
    __syncthreads();
    for (int d = t; d < DD; d += 256) {
        float acc = bc[d];
        const float* wrow = wc + (size_t)d * 192;
        #pragma unroll 8
        for (int i = 0; i < 192; i++) acc += patch[i] * wrow[i];
        h[(size_t)bn * DD + d] = acc + pos[(size_t)n * DD + d];
    }
}

// ---------------------------------------------------------------------------
// LayerNorm (output rounded to tf32 — feeds GEMM A operand)
// ---------------------------------------------------------------------------
__global__ void ln_kernel(const float* __restrict__ x,
                          const float* __restrict__ w,
                          const float* __restrict__ b,
                          float* __restrict__ y) {
    int row = blockIdx.x;
    const float* xr = x + (size_t)row * DD;
    __shared__ float red[256];
    int t = threadIdx.x;
    float v0 = xr[t], v1 = xr[t + 256], v2 = xr[t + 512];
    red[t] = v0 + v1 + v2;
    __syncthreads();
    #pragma unroll
    for (int s = 128; s > 0; s >>= 1) { if (t < s) red[t] += red[t + s]; __syncthreads(); }
    float mean = red[0] * (1.0f / DD);
    __syncthreads();
    float d0 = v0 - mean, d1 = v1 - mean, d2 = v2 - mean;
    red[t] = d0 * d0 + d1 * d1 + d2 * d2;
    __syncthreads();
    #pragma unroll
    for (int s = 128; s > 0; s >>= 1) { if (t < s) red[t] += red[t + s]; __syncthreads(); }
    float rstd = rsqrtf(red[0] * (1.0f / DD) + 1e-5f);
    float* yr = y + (size_t)row * DD;
    yr[t]       = tf32f(d0 * rstd * w[t]       + b[t]);
    yr[t + 256] = tf32f(d1 * rstd * w[t + 256] + b[t + 256]);
    yr[t + 512] = tf32f(d2 * rstd * w[t + 512] + b[t + 512]);
}

// ---------------------------------------------------------------------------
// tf32 GEMM: C[M,N] = epi(A[M,K] @ W[K,N]). Operands pre-rounded to tf32.
// BM=BN=128, BK=16, 4-stage cp.async. 256 threads = 8 warps (2x4),
// warp tile 64x32 (4x4 grid of m16n8k8). As[stage][128][20], Bs[stage][16][136].
// __launch_bounds__(256, 2): 2 blocks/SM (regs <= 128).
// ---------------------------------------------------------------------------
#define GSTAGES 4
#define GEMM_SMEM ((GSTAGES * 128 * 20 + GSTAGES * 16 * 136) * 4)

template <int BIAS, int GELU, int RES, int TF32OUT>
__global__ __launch_bounds__(256, 2)
void mma_gemm(const float* __restrict__ A, const float* __restrict__ W,
              const float* __restrict__ bias, const float* __restrict__ res,
              float* __restrict__ C, int K, int N) {
    extern __shared__ float smem[];
    float (*As)[128][20] = (float(*)[128][20])smem;
    float (*Bs)[16][136] = (float(*)[16][136])(smem + GSTAGES * 128 * 20);

    int tid = threadIdx.x, wid = tid >> 5, lane = tid & 31;
    int g = lane >> 2, tg = lane & 3;
    int warp_m = (wid >> 2) * 64, warp_n = (wid & 3) * 32;
    int bm0 = blockIdx.y * 128, bn0 = blockIdx.x * 128;

    float acc[4][4][4];
    #pragma unroll
    for (int i = 0; i < 4; i++)
        #pragma unroll
        for (int j = 0; j < 4; j++)
            #pragma unroll
            for (int r = 0; r < 4; r++) acc[i][j][r] = 0.f;

    const float* Abase = A + (size_t)bm0 * K;
    const float* Wbase = W + bn0;

    int am = tid >> 2, ak4 = tid & 3;          // A: 64 rows x 4 quads (x2)
    int bk = tid >> 5, bn4 = tid & 31;         // B: 8 rows x 32 quads (x2)

    auto issue = [&](int tile, int s) {
        int k0 = tile * 16;
        cp_async16(&As[s][am][ak4 * 4],       Abase + (size_t)am * K + k0 + ak4 * 4);
        cp_async16(&As[s][am + 64][ak4 * 4],  Abase + (size_t)(am + 64) * K + k0 + ak4 * 4);
        cp_async16(&Bs[s][bk][bn4 * 4],       Wbase + (size_t)(k0 + bk) * N + bn4 * 4);
        cp_async16(&Bs[s][bk + 8][bn4 * 4],   Wbase + (size_t)(k0 + bk + 8) * N + bn4 * 4);
        CP_COMMIT();
    };

    int niter = K / 16;
    issue(0, 0); issue(1, 1); issue(2, 2);

    for (int i = 0; i < niter; i++) {
        int rem = niter - i;
        if (rem >= 3)      CP_WAIT(2);
        else if (rem == 2) CP_WAIT(1);
        else               CP_WAIT(0);
        __syncthreads();
        if (i + 3 < niter) issue(i + 3, (i + 3) & 3);
        int s = i & 3;
        #pragma unroll
        for (int ks = 0; ks < 2; ks++) {
            int k8 = ks * 8;
            unsigned bf[4][2];
            #pragma unroll
            for (int tj = 0; tj < 4; tj++) {
                int nb = warp_n + tj * 8 + g;
                bf[tj][0] = __float_as_uint(Bs[s][k8 + tg][nb]);
                bf[tj][1] = __float_as_uint(Bs[s][k8 + tg + 4][nb]);
            }
            #pragma unroll
            for (int ti = 0; ti < 4; ti++) {
                int mb = warp_m + ti * 16 + g;
                unsigned af[4];
                af[0] = __float_as_uint(As[s][mb][k8 + tg]);
                af[1] = __float_as_uint(As[s][mb + 8][k8 + tg]);
                af[2] = __float_as_uint(As[s][mb][k8 + tg + 4]);
                af[3] = __float_as_uint(As[s][mb + 8][k8 + tg + 4]);
                #pragma unroll
                for (int tj = 0; tj < 4; tj++)
                    mma_tf32(acc[ti][tj], af, bf[tj]);
            }
        }
    }

    #pragma unroll
    for (int ti = 0; ti < 4; ti++) {
        #pragma unroll
        for (int tj = 0; tj < 4; tj++) {
            int r0 = bm0 + warp_m + ti * 16 + g;
            int r1 = r0 + 8;
            int cc = bn0 + warp_n + tj * 8 + tg * 2;
            float v0 = acc[ti][tj][0], v1 = acc[ti][tj][1];
            float v2 = acc[ti][tj][2], v3 = acc[ti][tj][3];
            if (BIAS) {
                float b0 = bias[cc], b1 = bias[cc + 1];
                v0 += b0; v1 += b1; v2 += b0; v3 += b1;
            }
            if (GELU) {
                v0 = gelu_f(v0); v1 = gelu_f(v1);
                v2 = gelu_f(v2); v3 = gelu_f(v3);
            }
            if (RES) {
                const float* p0 = res + (size_t)r0 * N + cc;
                const float* p1 = res + (size_t)r1 * N + cc;
                v0 += p0[0]; v1 += p0[1]; v2 += p1[0]; v3 += p1[1];
            }
            if (TF32OUT) {
                v0 = tf32f(v0); v1 = tf32f(v1); v2 = tf32f(v2); v3 = tf32f(v3);
            }
            float2 o0 = {v0, v1}, o1 = {v2, v3};
            *(float2*)&C[(size_t)r0 * N + cc] = o0;
            *(float2*)&C[(size_t)r1 * N + cc] = o1;
        }
    }
}

// ---------------------------------------------------------------------------
// Fused flash attention. One block = one (b, head, 128-row Q tile).
// 8 warps x 16 Q rows. 16 KV tiles of 64. Online softmax. Inputs pre-rounded.
// __launch_bounds__(256, 2): 2 blocks/SM.
// ---------------------------------------------------------------------------
#define FLASH_SMEM ((128 * 68 + 64 * 68 + 64 * 72 + 128 * 68) * 4)

__global__ __launch_bounds__(256, 2)
void flash_attn(const float* __restrict__ qkv, float* __restrict__ O) {
    extern __shared__ float fs[];
    float (*Qs)[68] = (float(*)[68])fs;
    float (*Ks)[68] = (float(*)[68])(fs + 128 * 68);
    float (*Vs)[72] = (float(*)[72])(fs + 128 * 68 + 64 * 68);
    float (*Ps)[68] = (float(*)[68])(fs + 128 * 68 + 64 * 68 + 64 * 72);

    int z = blockIdx.y, b = z / HEADS, hd = z % HEADS;
    const float* Qp = qkv + (size_t)b * NN_TOK * QKV_LD + hd * DH;
    const float* Kp = Qp + INNER;
    const float* Vp = Qp + 2 * INNER;
    int q0 = blockIdx.x * 128;

    int tid = threadIdx.x, wid = tid >> 5, lane = tid & 31;
    int g = lane >> 2, tg = lane & 3;
    int warp_m = wid * 16;

    int lr = tid >> 4, ld4 = tid & 15;

    auto issueK = [&](int j) {
        #pragma unroll
        for (int i = 0; i < 4; i++)
            cp_async16(&Ks[lr + i * 16][ld4 * 4],
                       Kp + (size_t)(j * 64 + lr + i * 16) * QKV_LD + ld4 * 4);
        CP_COMMIT();
    };
    auto issueV = [&](int j) {
        #pragma unroll
        for (int i = 0; i < 4; i++)
            cp_async16(&Vs[lr + i * 16][ld4 * 4],
                       Vp + (size_t)(j * 64 + lr + i * 16) * QKV_LD + ld4 * 4);
        CP_COMMIT();
    };

    #pragma unroll
    for (int i = 0; i < 8; i++)
        cp_async16(&Qs[lr + i * 16][ld4 * 4],
                   Qp + (size_t)(q0 + lr + i * 16) * QKV_LD + ld4 * 4);
    {
        #pragma unroll
        for (int i = 0; i < 4; i++)
            cp_async16(&Ks[lr + i * 16][ld4 * 4],
                       Kp + (size_t)(lr + i * 16) * QKV_LD + ld4 * 4);
        CP_COMMIT();
    }
    issueV(0);

    float m0 = -1e30f, m1 = -1e30f, l0 = 0.f, l1 = 0.f;
    float oa[8][4];
    #pragma unroll
    for (int tj = 0; tj < 8; tj++)
        #pragma unroll
        for (int r = 0; r < 4; r++) oa[tj][r] = 0.f;

    for (int j = 0; j < 16; j++) {
        CP_WAIT(1);
        __syncthreads();

        // S = Q @ K^T
        float sa[8][4];
        #pragma unroll
        for (int tj = 0; tj < 8; tj++)
            #pragma unroll
            for (int r = 0; r < 4; r++) sa[tj][r] = 0.f;
        #pragma unroll
        for (int k8 = 0; k8 < 64; k8 += 8) {
            unsigned af[4];
            af[0] = __float_as_uint(Qs[warp_m + g][k8 + tg]);
            af[1] = __float_as_uint(Qs[warp_m + g + 8][k8 + tg]);
            af[2] = __float_as_uint(Qs[warp_m + g][k8 + tg + 4]);
            af[3] = __float_as_uint(Qs[warp_m + g + 8][k8 + tg + 4]);
            #pragma unroll
            for (int tj = 0; tj < 8; tj++) {
                unsigned bf[2];
                bf[0] = __float_as_uint(Ks[tj * 8 + g][k8 + tg]);
                bf[1] = __float_as_uint(Ks[tj * 8 + g][k8 + tg + 4]);
                mma_tf32(sa[tj], af, bf);
            }
        }

        // Online softmax
        float mx0 = -1e30f, mx1 = -1e30f;
        #pragma unroll
        for (int tj = 0; tj < 8; tj++) {
            sa[tj][0] *= 0.125f; sa[tj][1] *= 0.125f;
            sa[tj][2] *= 0.125f; sa[tj][3] *= 0.125f;
            mx0 = fmaxf(mx0, fmaxf(sa[tj][0], sa[tj][1]));
            mx1 = fmaxf(mx1, fmaxf(sa[tj][2], sa[tj][3]));
        }
        mx0 = fmaxf(mx0, __shfl_xor_sync(0xffffffffu, mx0, 1));
        mx0 = fmaxf(mx0, __shfl_xor_sync(0xffffffffu, mx0, 2));
        mx1 = fmaxf(mx1, __shfl_xor_sync(0xffffffffu, mx1, 1));
        mx1 = fmaxf(mx1, __shfl_xor_sync(0xffffffffu, mx1, 2));
        float mn0 = fmaxf(m0, mx0), mn1 = fmaxf(m1, mx1);
        float a0 = __expf(m0 - mn0), a1 = __expf(m1 - mn1);
        float s0 = 0.f, s1 = 0.f;
        #pragma unroll
        for (int tj = 0; tj < 8; tj++) {
            float p0 = __expf(sa[tj][0] - mn0);
            float p1 = __expf(sa[tj][1] - mn0);
            float p2 = __expf(sa[tj][2] - mn1);
            float p3 = __expf(sa[tj][3] - mn1);
            s0 += p0 + p1; s1 += p2 + p3;
            Ps[warp_m + g][tj * 8 + 2 * tg]         = tf32f(p0);
            Ps[warp_m + g][tj * 8 + 2 * tg + 1]     = tf32f(p1);
            Ps[warp_m + g + 8][tj * 8 + 2 * tg]     = tf32f(p2);
            Ps[warp_m + g + 8][tj * 8 + 2 * tg + 1] = tf32f(p3);
            oa[tj][0] *= a0; oa[tj][1] *= a0;
            oa[tj][2] *= a1; oa[tj][3] *= a1;
        }
        s0 += __shfl_xor_sync(0xffffffffu, s0, 1);
        s0 += __shfl_xor_sync(0xffffffffu, s0, 2);
        s1 += __shfl_xor_sync(0xffffffffu, s1, 1);
        s1 += __shfl_xor_sync(0xffffffffu, s1, 2);
        l0 = l0 * a0 + s0; l1 = l1 * a1 + s1;
        m0 = mn0; m1 = mn1;

        __syncthreads();
        if (j < 15) issueK(j + 1);
        if (j < 15) { CP_WAIT(1); } else { CP_WAIT(0); }
        __syncthreads();

        // O += P @ V
        #pragma unroll
        for (int k8 = 0; k8 < 64; k8 += 8) {
            unsigned af[4];
            af[0] = __float_as_uint(Ps[warp_m + g][k8 + tg]);
            af[1] = __float_as_uint(Ps[warp_m + g + 8][k8 + tg]);
            af[2] = __float_as_uint(Ps[warp_m + g][k8 + tg + 4]);
            af[3] = __float_as_uint(Ps[warp_m + g + 8][k8 + tg + 4]);
            #pragma unroll
            for (int tj = 0; tj < 8; tj++) {
                unsigned bf[2];
                bf[0] = __float_as_uint(Vs[k8 + tg][tj * 8 + g]);
                bf[1] = __float_as_uint(Vs[k8 + tg + 4][tj * 8 + g]);
                mma_tf32(oa[tj], af, bf);
            }
        }
        __syncthreads();
        if (j < 15) issueV(j + 1);
    }

    // Normalize, round to tf32 (feeds out-proj GEMM), write O
    float i0 = 1.f / l0, i1 = 1.f / l1;
    int r0 = q0 + warp_m + g, r1 = r0 + 8;
    float* Ob = O + (size_t)b * NN_TOK * INNER + hd * DH;
    #pragma unroll
    for (int tj = 0; tj < 8; tj++) {
        int cc = tj * 8 + 2 * tg;
        float2 v0 = {tf32f(oa[tj][0] * i0), tf32f(oa[tj][1] * i0)};
        float2 v1 = {tf32f(oa[tj][2] * i1), tf32f(oa[tj][3] * i1)};
        *(float2*)&Ob[(size_t)r0 * INNER + cc] = v0;
        *(float2*)&Ob[(size_t)r1 * INNER + cc] = v1;
    }
}

// ---------------------------------------------------------------------------
extern "C" void kernel_launch(void* const* d_in, const int* in_sizes, int n_in,
                              void* d_out, int out_size) {
    const float* x      = (const float*)d_in[0];
    const float* w_conv = (const float*)d_in[1];
    const float* b_conv = (const float*)d_in[2];
    const float* pos    = (const float*)d_in[3];
    const float* ln1_w  = (const float*)d_in[4];
    const float* ln1_b  = (const float*)d_in[5];
    const float* qkv_w  = (const float*)d_in[6];
    const float* out_w  = (const float*)d_in[7];
    const float* out_b  = (const float*)d_in[8];
    const float* ln2_w  = (const float*)d_in[9];
    const float* ln2_b  = (const float*)d_in[10];
    const float* w1     = (const float*)d_in[11];
    const float* b1     = (const float*)d_in[12];
    const float* w2     = (const float*)d_in[13];
    const float* b2     = (const float*)d_in[14];

    float *h, *y, *qkv, *o, *mlp, *qw, *ow, *W1p, *W2p;
    cudaGetSymbolAddress((void**)&h,   g_h);
    cudaGetSymbolAddress((void**)&y,   g_y);
    cudaGetSymbolAddress((void**)&qkv, g_qkv);
    cudaGetSymbolAddress((void**)&o,   g_o);
    cudaGetSymbolAddress((void**)&mlp, g_mlp);
    cudaGetSymbolAddress((void**)&qw,  g_qw);
    cudaGetSymbolAddress((void**)&ow,  g_ow);
    cudaGetSymbolAddress((void**)&W1p, g_w1);
    cudaGetSymbolAddress((void**)&W2p, g_w2);

    // One-time: dynamic smem limits + full smem carveout (2 blocks/SM)
    static bool attrs_done = false;
    if (!attrs_done) {
        attrs_done = true;
        cudaFuncSetAttribute(mma_gemm<0,0,0,1>, cudaFuncAttributeMaxDynamicSharedMemorySize, GEMM_SMEM);
        cudaFuncSetAttribute(mma_gemm<1,0,1,0>, cudaFuncAttributeMaxDynamicSharedMemorySize, GEMM_SMEM);
        cudaFuncSetAttribute(mma_gemm<1,1,0,1>, cudaFuncAttributeMaxDynamicSharedMemorySize, GEMM_SMEM);
        cudaFuncSetAttribute(flash_attn,        cudaFuncAttributeMaxDynamicSharedMemorySize, FLASH_SMEM);
        cudaFuncSetAttribute(mma_gemm<0,0,0,1>, cudaFuncAttributePreferredSharedMemoryCarveout, 100);
        cudaFuncSetAttribute(mma_gemm<1,0,1,0>, cudaFuncAttributePreferredSharedMemoryCarveout, 100);
        cudaFuncSetAttribute(mma_gemm<1,1,0,1>, cudaFuncAttributePreferredSharedMemoryCarveout, 100);
        cudaFuncSetAttribute(flash_attn,        cudaFuncAttributePreferredSharedMemoryCarveout, 100);
    }

    // Pre-round all weights to tf32 (removes cvt from GEMM inner loops)
    {
        int n;
        n = DEPTH * DD * QKV_LD / 4;
        round_tf32_kernel<<<(n + 255) / 256, 256>>>(qkv_w, qw, n);
        n = DEPTH * INNER * DD / 4;
        round_tf32_kernel<<<(n + 255) / 256, 256>>>(out_w, ow, n);
        n = DEPTH * DD * MLPD / 4;
        round_tf32_kernel<<<(n + 255) / 256, 256>>>(w1, W1p, n);
        n = DEPTH * MLPD * DD / 4;
        round_tf32_kernel<<<(n + 255) / 256, 256>>>(w2, W2p, n);
    }

    patch_embed_kernel<<<M_ROWS, 256>>>(x, w_conv, b_conv, pos, h);

    for (int l = 0; l < DEPTH; l++) {
        const float* l1w = ln1_w + (size_t)l * DD;
        const float* l1b = ln1_b + (size_t)l * DD;
        const float* qwl = qw + (size_t)l * DD * QKV_LD;
        const float* owl = ow + (size_t)l * INNER * DD;
        const float* ob  = out_b + (size_t)l * DD;
        const float* l2w = ln2_w + (size_t)l * DD;
        const float* l2b = ln2_b + (size_t)l * DD;
        const float* W1l = W1p + (size_t)l * DD * MLPD;
        const float* B1  = b1 + (size_t)l * MLPD;
        const float* W2l = W2p + (size_t)l * MLPD * DD;
        const float* B2  = b2 + (size_t)l * DD;

        // PreNorm + QKV projection (tf32-rounded output feeds attention)
        ln_kernel<<<M_ROWS, 256>>>(h, l1w, l1b, y);
        mma_gemm<0,0,0,1><<<dim3(QKV_LD / 128, M_ROWS / 128), 256, GEMM_SMEM>>>(
            y, qwl, nullptr, nullptr, qkv, DD, QKV_LD);

        // Fused flash attention
        flash_attn<<<dim3(NN_TOK / 128, BB * HEADS), 256, FLASH_SMEM>>>(qkv, o);

        // Output projection + residual
        mma_gemm<1,0,1,0><<<dim3(DD / 128, M_ROWS / 128), 256, GEMM_SMEM>>>(
            o, owl, ob, h, h, INNER, DD);

        // PreNorm + FFN
        ln_kernel<<<M_ROWS, 256>>>(h, l2w, l2b, y);
        mma_gemm<1,1,0,1><<<dim3(MLPD / 128, M_ROWS / 128), 256, GEMM_SMEM>>>(
            y, W1l, B1, nullptr, mlp, DD, MLPD);
        float* cdst = (l == DEPTH - 1) ? (float*)d_out : h;
        mma_gemm<1,0,1,0><<<dim3(DD / 128, M_ROWS / 128), 256, GEMM_SMEM>>>(
            mlp, W2l, B2, h, cdst, MLPD, DD);
    }
}

// round 15
// speedup vs baseline: 1.3730x; 1.2283x over previous
#include <cuda_runtime.h>
#include <cuda_fp16.h>
#include <math.h>
#include <stdint.h>

// ---------------------------------------------------------------------------
// ViT encoder: B=8, N=1024 tokens, D=768, 8 layers, 12 heads x 64, MLP 3072.
// fp16 mma.sync (m16n8k16, fp32 accum) GEMMs + fp16 flash attention.
// Residual stream h stays fp32; all activations/weights fp16 (11-bit mantissa,
// same as tf32). Harness toolchain blocks tcgen05 (compute_103 PTX stage).
// ---------------------------------------------------------------------------

#define BB 8
#define NN_TOK 1024
#define DD 768
#define DEPTH 8
#define HEADS 12
#define DH 64
#define MLPD 3072
#define INNER 768
#define M_ROWS (BB * NN_TOK)          // 8192
#define QKV_LD (3 * INNER)            // 2304

// Scratch (device globals; allocation-free per harness rules)
__device__ float  g_h[M_ROWS * DD];
__device__ __half g_y[M_ROWS * DD];
__device__ __half g_qkv[M_ROWS * QKV_LD];
__device__ __half g_o[M_ROWS * INNER];
__device__ __half g_mlp[M_ROWS * MLPD];
// fp16, TRANSPOSED ([N][K]) weight copies
__device__ __half g_qw[DEPTH * DD * QKV_LD];
__device__ __half g_ow[DEPTH * INNER * DD];
__device__ __half g_w1[DEPTH * DD * MLPD];
__device__ __half g_w2[DEPTH * MLPD * DD];

__device__ __forceinline__ float gelu_f(float x) {
    return 0.5f * x * (1.0f + erff(x * 0.70710678118654752f));
}
__device__ __forceinline__ void mma_f16(float* d, const unsigned* a, const unsigned* b) {
    asm volatile(
        "mma.sync.aligned.m16n8k16.row.col.f32.f16.f16.f32 "
        "{%0,%1,%2,%3}, {%4,%5,%6,%7}, {%8,%9}, {%0,%1,%2,%3};\n"
        : "+f"(d[0]), "+f"(d[1]), "+f"(d[2]), "+f"(d[3])
        : "r"(a[0]), "r"(a[1]), "r"(a[2]), "r"(a[3]), "r"(b[0]), "r"(b[1]));
}
__device__ __forceinline__ void cp_async16(void* s, const void* g) {
    unsigned sa = (unsigned)__cvta_generic_to_shared(s);
    asm volatile("cp.async.cg.shared.global [%0], [%1], 16;\n" :: "r"(sa), "l"(g));
}
__device__ __forceinline__ void cp_async8(void* s, const void* g) {
    unsigned sa = (unsigned)__cvta_generic_to_shared(s);
    asm volatile("cp.async.ca.shared.global [%0], [%1], 8;\n" :: "r"(sa), "l"(g));
}
#define CP_COMMIT() asm volatile("cp.async.commit_group;\n" ::: "memory")
#define CP_WAIT(n)  asm volatile("cp.async.wait_group %0;\n" :: "n"(n) : "memory")

// ---------------------------------------------------------------------------
// Prep: transpose + fp16-round weights. src [K][N] f32 -> dst [N][K] f16.
// ---------------------------------------------------------------------------
__global__ void transpose_h_kernel(const float* __restrict__ src,
                                   __half* __restrict__ dst, int K, int N) {
    __shared__ float t[32][33];
    size_t off = (size_t)blockIdx.z * K * N;
    src += off; dst += off;
    int n0 = blockIdx.x * 32, k0 = blockIdx.y * 32;
    int tx = threadIdx.x, ty = threadIdx.y;   // 32 x 8
    #pragma unroll
    for (int i = 0; i < 32; i += 8)
        t[ty + i][tx] = src[(size_t)(k0 + ty + i) * N + n0 + tx];
    __syncthreads();
    #pragma unroll
    for (int i = 0; i < 32; i += 8)
        dst[(size_t)(n0 + ty + i) * K + k0 + tx] = __float2half_rn(t[tx][ty + i]);
}

// ---------------------------------------------------------------------------
// Patch embed (h stays fp32)
// ---------------------------------------------------------------------------
__global__ void patch_embed_kernel(const float* __restrict__ x,
                                   const float* __restrict__ wc,
                                   const float* __restrict__ bc,
                                   const float* __restrict__ pos,
                                   float* __restrict__ h) {
    int bn = blockIdx.x;
    int b = bn >> 10, n = bn & 1023;
    int py = n >> 5, px = n & 31;
    __shared__ float patch[192];
    int t = threadIdx.x;
    if (t < 192) {
        int c = t / 64, r = (t % 64) / 8, col = t % 8;
        patch[t] = x[(((size_t)b * 3 + c) * 256 + py * 8 + r) * 256 + px * 8 + col];
    }
    __syncthreads();
    for (int d = t; d < DD; d += 256) {
        float acc = bc[d];
        const float* wrow = wc + (size_t)d * 192;
        #pragma unroll 8
        for (int i = 0; i < 192; i++) acc += patch[i] * wrow[i];
        h[(size_t)bn * DD + d] = acc + pos[(size_t)n * DD + d];
    }
}

// ---------------------------------------------------------------------------
// LayerNorm: reads fp32 h, writes fp16 y
// ---------------------------------------------------------------------------
__global__ void ln_kernel(const float* __restrict__ x,
                          const float* __restrict__ w,
                          const float* __restrict__ b,
                          __half* __restrict__ y) {
    int row = blockIdx.x;
    const float* xr = x + (size_t)row * DD;
    __shared__ float red[256];
    int t = threadIdx.x;
    float v0 = xr[t], v1 = xr[t + 256], v2 = xr[t + 512];
    red[t] = v0 + v1 + v2;
    __syncthreads();
    #pragma unroll
    for (int s = 128; s > 0; s >>= 1) { if (t < s) red[t] += red[t + s]; __syncthreads(); }
    float mean = red[0] * (1.0f / DD);
    __syncthreads();
    float d0 = v0 - mean, d1 = v1 - mean, d2 = v2 - mean;
    red[t] = d0 * d0 + d1 * d1 + d2 * d2;
    __syncthreads();
    #pragma unroll
    for (int s = 128; s > 0; s >>= 1) { if (t < s) red[t] += red[t + s]; __syncthreads(); }
    float rstd = rsqrtf(red[0] * (1.0f / DD) + 1e-5f);
    __half* yr = y + (size_t)row * DD;
    yr[t]       = __float2half_rn(d0 * rstd * w[t]       + b[t]);
    yr[t + 256] = __float2half_rn(d1 * rstd * w[t + 256] + b[t + 256]);
    yr[t + 512] = __float2half_rn(d2 * rstd * w[t + 512] + b[t + 512]);
}

// ---------------------------------------------------------------------------
// fp16 GEMM: C[M,N] = epi(A[M,K] @ Wt[N,K]^T), fp32 accum.
// BM=BN=128, BK=32, 4-stage cp.async(8B). 256 thr = 8 warps (2x4),
// warp tile 64x32 via 4x4 m16n8k16. Smem rows pitch 40 halves (conflict-free).
// ---------------------------------------------------------------------------
#define PAH 40                              // pitch (halves)
#define GT_H (128 * PAH)                    // halves per tile
#define GSTAGES 4
#define GEMM_SMEM (2 * GSTAGES * GT_H * 2)  // bytes = 81920

template <int BIAS, int GELU, int RES, int OHALF>
__global__ __launch_bounds__(256, 2)
void hgemm(const __half* __restrict__ A, const __half* __restrict__ Wt,
           const float* __restrict__ bias, const float* __restrict__ res,
           void* __restrict__ Cout, int K, int N) {
    extern __shared__ __half hs[];
    int tid = threadIdx.x, wid = tid >> 5, lane = tid & 31;
    int g = lane >> 2, tg = lane & 3;
    int warp_m = (wid >> 2) * 64, warp_n = (wid & 3) * 32;
    int bm0 = blockIdx.y * 128, bn0 = blockIdx.x * 128;

    float acc[4][4][4];
    #pragma unroll
    for (int i = 0; i < 4; i++)
        #pragma unroll
        for (int j = 0; j < 4; j++)
            #pragma unroll
            for (int r = 0; r < 4; r++) acc[i][j][r] = 0.f;

    const __half* Ab = A  + (size_t)bm0 * K;
    const __half* Bb = Wt + (size_t)bn0 * K;

    auto issue = [&](int tile, int s) {
        int k0 = tile * 32;
        __half* as = hs + s * GT_H;
        __half* bs = hs + (GSTAGES + s) * GT_H;
        #pragma unroll
        for (int i = 0; i < 4; i++) {
            int idx = tid + i * 256;
            int r = idx >> 3, c = idx & 7;       // 128 rows x 8 chunks(8B)
            cp_async8(as + r * PAH + c * 4, Ab + (size_t)r * K + k0 + c * 4);
            cp_async8(bs + r * PAH + c * 4, Bb + (size_t)r * K + k0 + c * 4);
        }
        CP_COMMIT();
    };

    int niter = K / 32;
    issue(0, 0); issue(1, 1); issue(2, 2);

    for (int i = 0; i < niter; i++) {
        int rem = niter - i;
        if (rem >= 3)      CP_WAIT(2);
        else if (rem == 2) CP_WAIT(1);
        else               CP_WAIT(0);
        __syncthreads();
        if (i + 3 < niter) issue(i + 3, (i + 3) & 3);
        int s = i & 3;
        const __half* as = hs + s * GT_H;
        const __half* bs = hs + (GSTAGES + s) * GT_H;
        #pragma unroll
        for (int ks = 0; ks < 2; ks++) {
            int kh = ks * 16;
            unsigned bf[4][2];
            #pragma unroll
            for (int tj = 0; tj < 4; tj++) {
                const __half* br = bs + (warp_n + tj * 8 + g) * PAH + kh + 2 * tg;
                bf[tj][0] = *(const unsigned*)br;
                bf[tj][1] = *(const unsigned*)(br + 8);
            }
            #pragma unroll
            for (int ti = 0; ti < 4; ti++) {
                const __half* ar = as + (warp_m + ti * 16 + g) * PAH + kh + 2 * tg;
                unsigned af[4];
                af[0] = *(const unsigned*)ar;
                af[1] = *(const unsigned*)(ar + 8 * PAH);
                af[2] = *(const unsigned*)(ar + 8);
                af[3] = *(const unsigned*)(ar + 8 * PAH + 8);
                #pragma unroll
                for (int tj = 0; tj < 4; tj++)
                    mma_f16(acc[ti][tj], af, bf[tj]);
            }
        }
    }

    #pragma unroll
    for (int ti = 0; ti < 4; ti++) {
        #pragma unroll
        for (int tj = 0; tj < 4; tj++) {
            int r0 = bm0 + warp_m + ti * 16 + g;
            int r1 = r0 + 8;
            int cc = bn0 + warp_n + tj * 8 + tg * 2;
            float v0 = acc[ti][tj][0], v1 = acc[ti][tj][1];
            float v2 = acc[ti][tj][2], v3 = acc[ti][tj][3];
            if (BIAS) {
                float b0 = bias[cc], b1 = bias[cc + 1];
                v0 += b0; v1 += b1; v2 += b0; v3 += b1;
            }
            if (GELU) {
                v0 = gelu_f(v0); v1 = gelu_f(v1);
                v2 = gelu_f(v2); v3 = gelu_f(v3);
            }
            if (RES) {
                const float* p0 = res + (size_t)r0 * N + cc;
                const float* p1 = res + (size_t)r1 * N + cc;
                v0 += p0[0]; v1 += p0[1]; v2 += p1[0]; v3 += p1[1];
            }
            if (OHALF) {
                __half2* C = (__half2*)Cout;
                C[((size_t)r0 * N + cc) >> 1] = __floats2half2_rn(v0, v1);
                C[((size_t)r1 * N + cc) >> 1] = __floats2half2_rn(v2, v3);
            } else {
                float* C = (float*)Cout;
                float2 o0 = {v0, v1}, o1 = {v2, v3};
                *(float2*)&C[(size_t)r0 * N + cc] = o0;
                *(float2*)&C[(size_t)r1 * N + cc] = o1;
            }
        }
    }
}

// ---------------------------------------------------------------------------
// fp16 flash attention. One block = one (b, head, 128-row Q tile).
// 8 warps x 16 Q rows, 16 KV tiles of 64, online softmax (fp32), fp16 tiles.
// Smem pitch 72 halves (144B) -> conflict-free fragment reads.
// ---------------------------------------------------------------------------
#define FP 72
#define FLASH_SMEM ((128 * FP + 64 * FP + 64 * FP + 128 * FP) * 2)  // 55296 B

__global__ __launch_bounds__(256, 2)
void flash_attn(const __half* __restrict__ qkv, __half* __restrict__ O) {
    extern __shared__ __half fh[];
    __half* Qs = fh;                       // [128][FP]
    __half* Ks = fh + 128 * FP;            // [64][FP]
    __half* Vs = fh + 192 * FP;            // [64][FP]
    __half* Ps = fh + 256 * FP;            // [128][FP]

    int z = blockIdx.y, b = z / HEADS, hd = z % HEADS;
    const __half* Qp = qkv + (size_t)b * NN_TOK * QKV_LD + hd * DH;
    const __half* Kp = Qp + INNER;
    const __half* Vp = Qp + 2 * INNER;
    int q0 = blockIdx.x * 128;

    int tid = threadIdx.x, wid = tid >> 5, lane = tid & 31;
    int g = lane >> 2, tg = lane & 3;
    int warp_m = wid * 16;

    auto issueK = [&](int j) {
        #pragma unroll
        for (int i = 0; i < 2; i++) {
            int idx = tid + i * 256;
            int r = idx >> 3, c = idx & 7;     // 64 rows x 8 chunks(16B)
            cp_async16(Ks + r * FP + c * 8,
                       Kp + (size_t)(j * 64 + r) * QKV_LD + c * 8);
        }
        CP_COMMIT();
    };
    auto issueV = [&](int j) {
        #pragma unroll
        for (int i = 0; i < 2; i++) {
            int idx = tid + i * 256;
            int r = idx >> 3, c = idx & 7;
            cp_async16(Vs + r * FP + c * 8,
                       Vp + (size_t)(j * 64 + r) * QKV_LD + c * 8);
        }
        CP_COMMIT();
    };

    // Group 0: Q + K0.  Group 1: V0.
    {
        #pragma unroll
        for (int i = 0; i < 4; i++) {
            int idx = tid + i * 256;
            int r = idx >> 3, c = idx & 7;     // 128 rows x 8 chunks
            cp_async16(Qs + r * FP + c * 8,
                       Qp + (size_t)(q0 + r) * QKV_LD + c * 8);
        }
        #pragma unroll
        for (int i = 0; i < 2; i++) {
            int idx = tid + i * 256;
            int r = idx >> 3, c = idx & 7;
            cp_async16(Ks + r * FP + c * 8, Kp + (size_t)r * QKV_LD + c * 8);
        }
        CP_COMMIT();
    }
    issueV(0);

    float m0 = -1e30f, m1 = -1e30f, l0 = 0.f, l1 = 0.f;
    float oa[8][4];
    #pragma unroll
    for (int tj = 0; tj < 8; tj++)
        #pragma unroll
        for (int r = 0; r < 4; r++) oa[tj][r] = 0.f;

    for (int j = 0; j < 16; j++) {
        CP_WAIT(1);
        __syncthreads();

        // S = Q @ K^T  (m16n8k16, 4 K-steps over DH=64)
        float sa[8][4];
        #pragma unroll
        for (int tj = 0; tj < 8; tj++)
            #pragma unroll
            for (int r = 0; r < 4; r++) sa[tj][r] = 0.f;
        #pragma unroll
        for (int k16 = 0; k16 < 64; k16 += 16) {
            const __half* qr = Qs + (warp_m + g) * FP + k16 + 2 * tg;
            unsigned af[4];
            af[0] = *(const unsigned*)qr;
            af[1] = *(const unsigned*)(qr + 8 * FP);
            af[2] = *(const unsigned*)(qr + 8);
            af[3] = *(const unsigned*)(qr + 8 * FP + 8);
            #pragma unroll
            for (int tj = 0; tj < 8; tj++) {
                const __half* kr = Ks + (tj * 8 + g) * FP + k16 + 2 * tg;
                unsigned bf[2];
                bf[0] = *(const unsigned*)kr;
                bf[1] = *(const unsigned*)(kr + 8);
                mma_f16(sa[tj], af, bf);
            }
        }

        // Online softmax (fp32)
        float mx0 = -1e30f, mx1 = -1e30f;
        #pragma unroll
        for (int tj = 0; tj < 8; tj++) {
            sa[tj][0] *= 0.125f; sa[tj][1] *= 0.125f;
            sa[tj][2] *= 0.125f; sa[tj][3] *= 0.125f;
            mx0 = fmaxf(mx0, fmaxf(sa[tj][0], sa[tj][1]));
            mx1 = fmaxf(mx1, fmaxf(sa[tj][2], sa[tj][3]));
        }
        mx0 = fmaxf(mx0, __shfl_xor_sync(0xffffffffu, mx0, 1));
        mx0 = fmaxf(mx0, __shfl_xor_sync(0xffffffffu, mx0, 2));
        mx1 = fmaxf(mx1, __shfl_xor_sync(0xffffffffu, mx1, 1));
        mx1 = fmaxf(mx1, __shfl_xor_sync(0xffffffffu, mx1, 2));
        float mn0 = fmaxf(m0, mx0), mn1 = fmaxf(m1, mx1);
        float a0 = __expf(m0 - mn0), a1 = __expf(m1 - mn1);
        float s0 = 0.f, s1 = 0.f;
        #pragma unroll
        for (int tj = 0; tj < 8; tj++) {
            float p0 = __expf(sa[tj][0] - mn0);
            float p1 = __expf(sa[tj][1] - mn0);
            float p2 = __expf(sa[tj][2] - mn1);
            float p3 = __expf(sa[tj][3] - mn1);
            s0 += p0 + p1; s1 += p2 + p3;
            *(__half2*)(Ps + (warp_m + g) * FP + tj * 8 + 2 * tg) =
                __floats2half2_rn(p0, p1);
            *(__half2*)(Ps + (warp_m + g + 8) * FP + tj * 8 + 2 * tg) =
                __floats2half2_rn(p2, p3);
            oa[tj][0] *= a0; oa[tj][1] *= a0;
            oa[tj][2] *= a1; oa[tj][3] *= a1;
        }
        s0 += __shfl_xor_sync(0xffffffffu, s0, 1);
        s0 += __shfl_xor_sync(0xffffffffu, s0, 2);
        s1 += __shfl_xor_sync(0xffffffffu, s1, 1);
        s1 += __shfl_xor_sync(0xffffffffu, s1, 2);
        l0 = l0 * a0 + s0; l1 = l1 * a1 + s1;
        m0 = mn0; m1 = mn1;

        __syncthreads();                 // Ks consumed; Ps visible
        if (j < 15) issueK(j + 1);
        if (j < 15) { CP_WAIT(1); } else { CP_WAIT(0); }   // V_j arrived
        __syncthreads();

        // O += P @ V  (V fragment K-pairs read as 16-bit scalars + pack)
        #pragma unroll
        for (int k16 = 0; k16 < 64; k16 += 16) {
            const __half* pr = Ps + (warp_m + g) * FP + k16 + 2 * tg;
            unsigned af[4];
            af[0] = *(const unsigned*)pr;
            af[1] = *(const unsigned*)(pr + 8 * FP);
            af[2] = *(const unsigned*)(pr + 8);
            af[3] = *(const unsigned*)(pr + 8 * FP + 8);
            #pragma unroll
            for (int tj = 0; tj < 8; tj++) {
                int col = tj * 8 + g;
                const __half* v0 = Vs + (k16 + 2 * tg) * FP + col;
                unsigned b0 = (unsigned)__half_as_ushort(v0[0]) |
                              ((unsigned)__half_as_ushort(v0[FP]) << 16);
                const __half* v1 = v0 + 8 * FP;
                unsigned b1 = (unsigned)__half_as_ushort(v1[0]) |
                              ((unsigned)__half_as_ushort(v1[FP]) << 16);
                unsigned bf[2] = {b0, b1};
                mma_f16(oa[tj], af, bf);
            }
        }
        __syncthreads();                 // Vs consumed
        if (j < 15) issueV(j + 1);
    }

    // Normalize, write fp16 O
    float i0 = 1.f / l0, i1 = 1.f / l1;
    int r0 = q0 + warp_m + g, r1 = r0 + 8;
    __half* Ob = O + (size_t)b * NN_TOK * INNER + hd * DH;
    #pragma unroll
    for (int tj = 0; tj < 8; tj++) {
        int cc = tj * 8 + 2 * tg;
        *(__half2*)(Ob + (size_t)r0 * INNER + cc) =
            __floats2half2_rn(oa[tj][0] * i0, oa[tj][1] * i0);
        *(__half2*)(Ob + (size_t)r1 * INNER + cc) =
            __floats2half2_rn(oa[tj][2] * i1, oa[tj][3] * i1);
    }
}

// ---------------------------------------------------------------------------
extern "C" void kernel_launch(void* const* d_in, const int* in_sizes, int n_in,
                              void* d_out, int out_size) {
    const float* x      = (const float*)d_in[0];
    const float* w_conv = (const float*)d_in[1];
    const float* b_conv = (const float*)d_in[2];
    const float* pos    = (const float*)d_in[3];
    const float* ln1_w  = (const float*)d_in[4];
    const float* ln1_b  = (const float*)d_in[5];
    const float* qkv_w  = (const float*)d_in[6];
    const float* out_w  = (const float*)d_in[7];
    const float* out_b  = (const float*)d_in[8];
    const float* ln2_w  = (const float*)d_in[9];
    const float* ln2_b  = (const float*)d_in[10];
    const float* w1     = (const float*)d_in[11];
    const float* b1     = (const float*)d_in[12];
    const float* w2     = (const float*)d_in[13];
    const float* b2     = (const float*)d_in[14];

    float* h;
    __half *y, *qkv, *o, *mlp, *qw, *ow, *W1p, *W2p;
    cudaGetSymbolAddress((void**)&h,   g_h);
    cudaGetSymbolAddress((void**)&y,   g_y);
    cudaGetSymbolAddress((void**)&qkv, g_qkv);
    cudaGetSymbolAddress((void**)&o,   g_o);
    cudaGetSymbolAddress((void**)&mlp, g_mlp);
    cudaGetSymbolAddress((void**)&qw,  g_qw);
    cudaGetSymbolAddress((void**)&ow,  g_ow);
    cudaGetSymbolAddress((void**)&W1p, g_w1);
    cudaGetSymbolAddress((void**)&W2p, g_w2);

    static bool attrs_done = false;
    if (!attrs_done) {
        attrs_done = true;
        cudaFuncSetAttribute(hgemm<0,0,0,1>, cudaFuncAttributeMaxDynamicSharedMemorySize, GEMM_SMEM);
        cudaFuncSetAttribute(hgemm<1,0,1,0>, cudaFuncAttributeMaxDynamicSharedMemorySize, GEMM_SMEM);
        cudaFuncSetAttribute(hgemm<1,1,0,1>, cudaFuncAttributeMaxDynamicSharedMemorySize, GEMM_SMEM);
        cudaFuncSetAttribute(flash_attn,     cudaFuncAttributeMaxDynamicSharedMemorySize, FLASH_SMEM);
        cudaFuncSetAttribute(hgemm<0,0,0,1>, cudaFuncAttributePreferredSharedMemoryCarveout, 100);
        cudaFuncSetAttribute(hgemm<1,0,1,0>, cudaFuncAttributePreferredSharedMemoryCarveout, 100);
        cudaFuncSetAttribute(hgemm<1,1,0,1>, cudaFuncAttributePreferredSharedMemoryCarveout, 100);
        cudaFuncSetAttribute(flash_attn,     cudaFuncAttributePreferredSharedMemoryCarveout, 100);
    }

    // Prep: transpose + fp16-round all weights ([K][N] f32 -> [N][K] f16)
    {
        dim3 blk(32, 8);
        transpose_h_kernel<<<dim3(QKV_LD / 32, DD / 32, DEPTH), blk>>>(qkv_w, qw, DD, QKV_LD);
        transpose_h_kernel<<<dim3(DD / 32, INNER / 32, DEPTH), blk>>>(out_w, ow, INNER, DD);
        transpose_h_kernel<<<dim3(MLPD / 32, DD / 32, DEPTH), blk>>>(w1, W1p, DD, MLPD);
        transpose_h_kernel<<<dim3(DD / 32, MLPD / 32, DEPTH), blk>>>(w2, W2p, MLPD, DD);
    }

    patch_embed_kernel<<<M_ROWS, 256>>>(x, w_conv, b_conv, pos, h);

    for (int l = 0; l < DEPTH; l++) {
        const float*  l1w = ln1_w + (size_t)l * DD;
        const float*  l1b = ln1_b + (size_t)l * DD;
        const __half* qwl = qw + (size_t)l * DD * QKV_LD;
        const __half* owl = ow + (size_t)l * INNER * DD;
        const float*  ob  = out_b + (size_t)l * DD;
        const float*  l2w = ln2_w + (size_t)l * DD;
        const float*  l2b = ln2_b + (size_t)l * DD;
        const __half* W1l = W1p + (size_t)l * DD * MLPD;
        const float*  B1  = b1 + (size_t)l * MLPD;
        const __half* W2l = W2p + (size_t)l * MLPD * DD;
        const float*  B2  = b2 + (size_t)l * DD;

        // PreNorm + QKV projection (fp16 out feeds attention)
        ln_kernel<<<M_ROWS, 256>>>(h, l1w, l1b, y);
        hgemm<0,0,0,1><<<dim3(QKV_LD / 128, M_ROWS / 128), 256, GEMM_SMEM>>>(
            y, qwl, nullptr, nullptr, qkv, DD, QKV_LD);

        // Fused flash attention (fp16)
        flash_attn<<<dim3(NN_TOK / 128, BB * HEADS), 256, FLASH_SMEM>>>(qkv, o);

        // Output projection + residual (fp32 out into h)
        hgemm<1,0,1,0><<<dim3(DD / 128, M_ROWS / 128), 256, GEMM_SMEM>>>(
            o, owl, ob, h, h, INNER, DD);

        // PreNorm + FFN
        ln_kernel<<<M_ROWS, 256>>>(h, l2w, l2b, y);
        hgemm<1,1,0,1><<<dim3(MLPD / 128, M_ROWS / 128), 256, GEMM_SMEM>>>(
            y, W1l, B1, nullptr, mlp, DD, MLPD);
        void* cdst = (l == DEPTH - 1) ? d_out : (void*)h;
        hgemm<1,0,1,0><<<dim3(DD / 128, M_ROWS / 128), 256, GEMM_SMEM>>>(
            mlp, W2l, B2, h, cdst, MLPD, DD);
    }
}

// round 17
// speedup vs baseline: 1.4513x; 1.0571x over previous
#include <cuda_runtime.h>
#include <cuda_fp16.h>
#include <math.h>
#include <stdint.h>

// ---------------------------------------------------------------------------
// ViT encoder: B=8, N=1024 tokens, D=768, 8 layers, 12 heads x 64, MLP 3072.
// fp16 mma.sync (m16n8k16, fp32 accum) + ldmatrix fragment loads.
// Residual stream h stays fp32. tcgen05 unreachable (compute_103 PTX stage).
// ---------------------------------------------------------------------------

#define BB 8
#define NN_TOK 1024
#define DD 768
#define DEPTH 8
#define HEADS 12
#define DH 64
#define MLPD 3072
#define INNER 768
#define M_ROWS (BB * NN_TOK)          // 8192
#define QKV_LD (3 * INNER)            // 2304

// Scratch (device globals; allocation-free per harness rules)
__device__ float  g_h[M_ROWS * DD];
__device__ __half g_y[M_ROWS * DD];
__device__ __half g_qkv[M_ROWS * QKV_LD];
__device__ __half g_o[M_ROWS * INNER];
__device__ __half g_mlp[M_ROWS * MLPD];
// fp16, TRANSPOSED ([N][K]) weight copies
__device__ __half g_qw[DEPTH * DD * QKV_LD];
__device__ __half g_ow[DEPTH * INNER * DD];
__device__ __half g_w1[DEPTH * DD * MLPD];
__device__ __half g_w2[DEPTH * MLPD * DD];

__device__ __forceinline__ float gelu_f(float x) {
    return 0.5f * x * (1.0f + erff(x * 0.70710678118654752f));
}
__device__ __forceinline__ void mma_f16(float* d, const unsigned* a, const unsigned* b) {
    asm volatile(
        "mma.sync.aligned.m16n8k16.row.col.f32.f16.f16.f32 "
        "{%0,%1,%2,%3}, {%4,%5,%6,%7}, {%8,%9}, {%0,%1,%2,%3};\n"
        : "+f"(d[0]), "+f"(d[1]), "+f"(d[2]), "+f"(d[3])
        : "r"(a[0]), "r"(a[1]), "r"(a[2]), "r"(a[3]), "r"(b[0]), "r"(b[1]));
}
__device__ __forceinline__ void ldsm_x4(unsigned& r0, unsigned& r1,
                                        unsigned& r2, unsigned& r3, uint32_t a) {
    asm volatile("ldmatrix.sync.aligned.m8n8.x4.shared.b16 {%0,%1,%2,%3}, [%4];"
                 : "=r"(r0), "=r"(r1), "=r"(r2), "=r"(r3) : "r"(a));
}
__device__ __forceinline__ void ldsm_x4_t(unsigned& r0, unsigned& r1,
                                          unsigned& r2, unsigned& r3, uint32_t a) {
    asm volatile("ldmatrix.sync.aligned.m8n8.x4.trans.shared.b16 {%0,%1,%2,%3}, [%4];"
                 : "=r"(r0), "=r"(r1), "=r"(r2), "=r"(r3) : "r"(a));
}
__device__ __forceinline__ void cp_async16(void* s, const void* g) {
    unsigned sa = (unsigned)__cvta_generic_to_shared(s);
    asm volatile("cp.async.cg.shared.global [%0], [%1], 16;\n" :: "r"(sa), "l"(g));
}
__device__ __forceinline__ void cp_async8(void* s, const void* g) {
    unsigned sa = (unsigned)__cvta_generic_to_shared(s);
    asm volatile("cp.async.ca.shared.global [%0], [%1], 8;\n" :: "r"(sa), "l"(g));
}
#define CP_COMMIT() asm volatile("cp.async.commit_group;\n" ::: "memory")
#define CP_WAIT(n)  asm volatile("cp.async.wait_group %0;\n" :: "n"(n) : "memory")

// ---------------------------------------------------------------------------
// Prep: transpose + fp16-round weights. src [K][N] f32 -> dst [N][K] f16.
// ---------------------------------------------------------------------------
__global__ void transpose_h_kernel(const float* __restrict__ src,
                                   __half* __restrict__ dst, int K, int N) {
    __shared__ float t[32][33];
    size_t off = (size_t)blockIdx.z * K * N;
    src += off; dst += off;
    int n0 = blockIdx.x * 32, k0 = blockIdx.y * 32;
    int tx = threadIdx.x, ty = threadIdx.y;   // 32 x 8
    #pragma unroll
    for (int i = 0; i < 32; i += 8)
        t[ty + i][tx] = src[(size_t)(k0 + ty + i) * N + n0 + tx];
    __syncthreads();
    #pragma unroll
    for (int i = 0; i < 32; i += 8)
        dst[(size_t)(n0 + ty + i) * K + k0 + tx] = __float2half_rn(t[tx][ty + i]);
}

// ---------------------------------------------------------------------------
// Patch embed (h stays fp32)
// ---------------------------------------------------------------------------
__global__ void patch_embed_kernel(const float* __restrict__ x,
                                   const float* __restrict__ wc,
                                   const float* __restrict__ bc,
                                   const float* __restrict__ pos,
                                   float* __restrict__ h) {
    int bn = blockIdx.x;
    int b = bn >> 10, n = bn & 1023;
    int py = n >> 5, px = n & 31;
    __shared__ float patch[192];
    int t = threadIdx.x;
    if (t < 192) {
        int c = t / 64, r = (t % 64) / 8, col = t % 8;
        patch[t] = x[(((size_t)b * 3 + c) * 256 + py * 8 + r) * 256 + px * 8 + col];
    }
    __syncthreads();
    for (int d = t; d < DD; d += 256) {
        float acc = bc[d];
        const float* wrow = wc + (size_t)d * 192;
        #pragma unroll 8
        for (int i = 0; i < 192; i++) acc += patch[i] * wrow[i];
        h[(size_t)bn * DD + d] = acc + pos[(size_t)n * DD + d];
    }
}

// ---------------------------------------------------------------------------
// LayerNorm: reads fp32 h, writes fp16 y
// ---------------------------------------------------------------------------
__global__ void ln_kernel(const float* __restrict__ x,
                          const float* __restrict__ w,
                          const float* __restrict__ b,
                          __half* __restrict__ y) {
    int row = blockIdx.x;
    const float* xr = x + (size_t)row * DD;
    __shared__ float red[256];
    int t = threadIdx.x;
    float v0 = xr[t], v1 = xr[t + 256], v2 = xr[t + 512];
    red[t] = v0 + v1 + v2;
    __syncthreads();
    #pragma unroll
    for (int s = 128; s > 0; s >>= 1) { if (t < s) red[t] += red[t + s]; __syncthreads(); }
    float mean = red[0] * (1.0f / DD);
    __syncthreads();
    float d0 = v0 - mean, d1 = v1 - mean, d2 = v2 - mean;
    red[t] = d0 * d0 + d1 * d1 + d2 * d2;
    __syncthreads();
    #pragma unroll
    for (int s = 128; s > 0; s >>= 1) { if (t < s) red[t] += red[t + s]; __syncthreads(); }
    float rstd = rsqrtf(red[0] * (1.0f / DD) + 1e-5f);
    __half* yr = y + (size_t)row * DD;
    yr[t]       = __float2half_rn(d0 * rstd * w[t]       + b[t]);
    yr[t + 256] = __float2half_rn(d1 * rstd * w[t + 256] + b[t + 256]);
    yr[t + 512] = __float2half_rn(d2 * rstd * w[t + 512] + b[t + 512]);
}

// ---------------------------------------------------------------------------
// fp16 GEMM: C[M,N] = epi(A[M,K] @ Wt[N,K]^T), fp32 accum, ldmatrix frags.
// BM=BN=128, BK=32, 4-stage cp.async(8B). 256 thr = 8 warps (2x4),
// warp tile 64x32. Pitch 40 halves (80B) -> LDSM conflict-free.
// ---------------------------------------------------------------------------
#define PAH 40                              // pitch (halves)
#define GT_H (128 * PAH)                    // halves per tile
#define GSTAGES 4
#define GEMM_SMEM (2 * GSTAGES * GT_H * 2)  // bytes = 81920

template <int BIAS, int GELU, int RES, int OHALF>
__global__ __launch_bounds__(256, 2)
void hgemm(const __half* __restrict__ A, const __half* __restrict__ Wt,
           const float* __restrict__ bias, const float* __restrict__ res,
           void* __restrict__ Cout, int K, int N) {
    extern __shared__ __half hs[];
    int tid = threadIdx.x, wid = tid >> 5, lane = tid & 31;
    int g = lane >> 2, tg = lane & 3;
    int warp_m = (wid >> 2) * 64, warp_n = (wid & 3) * 32;
    int bm0 = blockIdx.y * 128, bn0 = blockIdx.x * 128;

    float acc[4][4][4];
    #pragma unroll
    for (int i = 0; i < 4; i++)
        #pragma unroll
        for (int j = 0; j < 4; j++)
            #pragma unroll
            for (int r = 0; r < 4; r++) acc[i][j][r] = 0.f;

    const __half* Ab = A  + (size_t)bm0 * K;
    const __half* Bb = Wt + (size_t)bn0 * K;

    auto issue = [&](int tile, int s) {
        int k0 = tile * 32;
        __half* as = hs + s * GT_H;
        __half* bs = hs + (GSTAGES + s) * GT_H;
        #pragma unroll
        for (int i = 0; i < 4; i++) {
            int idx = tid + i * 256;
            int r = idx >> 3, c = idx & 7;       // 128 rows x 8 chunks(8B)
            cp_async8(as + r * PAH + c * 4, Ab + (size_t)r * K + k0 + c * 4);
            cp_async8(bs + r * PAH + c * 4, Bb + (size_t)r * K + k0 + c * 4);
        }
        CP_COMMIT();
    };

    // ldmatrix per-lane source rows (bytes)
    uint32_t hsh = (uint32_t)__cvta_generic_to_shared(hs);
    int l7 = lane & 7, l8 = (lane >> 3) & 1, l16 = lane >> 4;
    uint32_t aoff = ((warp_m + l7 + l8 * 8) * PAH + l16 * 8) * 2;
    uint32_t boff = ((warp_n + l16 * 8 + l7) * PAH + l8 * 8) * 2;

    int niter = K / 32;
    issue(0, 0); issue(1, 1); issue(2, 2);

    for (int i = 0; i < niter; i++) {
        int rem = niter - i;
        if (rem >= 3)      CP_WAIT(2);
        else if (rem == 2) CP_WAIT(1);
        else               CP_WAIT(0);
        __syncthreads();
        if (i + 3 < niter) issue(i + 3, (i + 3) & 3);
        int s = i & 3;
        uint32_t as_b = hsh + s * GT_H * 2 + aoff;
        uint32_t bs_b = hsh + (GSTAGES + s) * GT_H * 2 + boff;
        #pragma unroll
        for (int ks = 0; ks < 2; ks++) {
            unsigned bf[4][2];
            #pragma unroll
            for (int tp = 0; tp < 2; tp++)
                ldsm_x4(bf[2*tp][0], bf[2*tp][1], bf[2*tp+1][0], bf[2*tp+1][1],
                        bs_b + tp * (16 * PAH * 2) + ks * 32);
            #pragma unroll
            for (int ti = 0; ti < 4; ti++) {
                unsigned af[4];
                ldsm_x4(af[0], af[1], af[2], af[3],
                        as_b + ti * (16 * PAH * 2) + ks * 32);
                #pragma unroll
                for (int tj = 0; tj < 4; tj++)
                    mma_f16(acc[ti][tj], af, bf[tj]);
            }
        }
    }

    #pragma unroll
    for (int ti = 0; ti < 4; ti++) {
        #pragma unroll
        for (int tj = 0; tj < 4; tj++) {
            int r0 = bm0 + warp_m + ti * 16 + g;
            int r1 = r0 + 8;
            int cc = bn0 + warp_n + tj * 8 + tg * 2;
            float v0 = acc[ti][tj][0], v1 = acc[ti][tj][1];
            float v2 = acc[ti][tj][2], v3 = acc[ti][tj][3];
            if (BIAS) {
                float b0 = bias[cc], b1 = bias[cc + 1];
                v0 += b0; v1 += b1; v2 += b0; v3 += b1;
            }
            if (GELU) {
                v0 = gelu_f(v0); v1 = gelu_f(v1);
                v2 = gelu_f(v2); v3 = gelu_f(v3);
            }
            if (RES) {
                const float* p0 = res + (size_t)r0 * N + cc;
                const float* p1 = res + (size_t)r1 * N + cc;
                v0 += p0[0]; v1 += p0[1]; v2 += p1[0]; v3 += p1[1];
            }
            if (OHALF) {
                __half2* C = (__half2*)Cout;
                C[((size_t)r0 * N + cc) >> 1] = __floats2half2_rn(v0, v1);
                C[((size_t)r1 * N + cc) >> 1] = __floats2half2_rn(v2, v3);
            } else {
                float* C = (float*)Cout;
                float2 o0 = {v0, v1}, o1 = {v2, v3};
                *(float2*)&C[(size_t)r0 * N + cc] = o0;
                *(float2*)&C[(size_t)r1 * N + cc] = o1;
            }
        }
    }
}

// ---------------------------------------------------------------------------
// fp16 flash attention, ldmatrix frags. One block = (b, head, 128 Q rows).
// 8 warps x 16 Q rows, 16 KV tiles of 64, online softmax fp32.
// Pitch 72 halves (144B) -> LDSM conflict-free (incl. trans for V).
// ---------------------------------------------------------------------------
#define FP 72
#define FLASH_SMEM ((128 * FP + 64 * FP + 64 * FP + 128 * FP) * 2)  // 55296 B

__global__ __launch_bounds__(256, 2)
void flash_attn(const __half* __restrict__ qkv, __half* __restrict__ O) {
    extern __shared__ __half fh[];
    __half* Qs = fh;                       // [128][FP]
    __half* Ks = fh + 128 * FP;            // [64][FP]
    __half* Vs = fh + 192 * FP;            // [64][FP]
    __half* Ps = fh + 256 * FP;            // [128][FP]

    int z = blockIdx.y, b = z / HEADS, hd = z % HEADS;
    const __half* Qp = qkv + (size_t)b * NN_TOK * QKV_LD + hd * DH;
    const __half* Kp = Qp + INNER;
    const __half* Vp = Qp + 2 * INNER;
    int q0 = blockIdx.x * 128;

    int tid = threadIdx.x, wid = tid >> 5, lane = tid & 31;
    int g = lane >> 2, tg = lane & 3;
    int warp_m = wid * 16;

    auto issueK = [&](int j) {
        #pragma unroll
        for (int i = 0; i < 2; i++) {
            int idx = tid + i * 256;
            int r = idx >> 3, c = idx & 7;
            cp_async16(Ks + r * FP + c * 8,
                       Kp + (size_t)(j * 64 + r) * QKV_LD + c * 8);
        }
        CP_COMMIT();
    };
    auto issueV = [&](int j) {
        #pragma unroll
        for (int i = 0; i < 2; i++) {
            int idx = tid + i * 256;
            int r = idx >> 3, c = idx & 7;
            cp_async16(Vs + r * FP + c * 8,
                       Vp + (size_t)(j * 64 + r) * QKV_LD + c * 8);
        }
        CP_COMMIT();
    };

    {
        #pragma unroll
        for (int i = 0; i < 4; i++) {
            int idx = tid + i * 256;
            int r = idx >> 3, c = idx & 7;
            cp_async16(Qs + r * FP + c * 8,
                       Qp + (size_t)(q0 + r) * QKV_LD + c * 8);
        }
        #pragma unroll
        for (int i = 0; i < 2; i++) {
            int idx = tid + i * 256;
            int r = idx >> 3, c = idx & 7;
            cp_async16(Ks + r * FP + c * 8, Kp + (size_t)r * QKV_LD + c * 8);
        }
        CP_COMMIT();
    }
    issueV(0);

    // ldmatrix per-lane offsets (bytes)
    uint32_t fsh = (uint32_t)__cvta_generic_to_shared(fh);
    uint32_t Qb = fsh, Kb = fsh + 128 * FP * 2, Vb = fsh + 192 * FP * 2,
             Pb = fsh + 256 * FP * 2;
    int l7 = lane & 7, l8 = (lane >> 3) & 1, l16 = lane >> 4;
    uint32_t qoff = ((warp_m + l7 + l8 * 8) * FP + l16 * 8) * 2;   // A-style
    uint32_t koff = ((l16 * 8 + l7) * FP + l8 * 8) * 2;            // B-style
    uint32_t voff = ((l8 * 8 + l7) * FP + l16 * 8) * 2;            // B-trans

    float m0 = -1e30f, m1 = -1e30f, l0 = 0.f, l1 = 0.f;
    float oa[8][4];
    #pragma unroll
    for (int tj = 0; tj < 8; tj++)
        #pragma unroll
        for (int r = 0; r < 4; r++) oa[tj][r] = 0.f;

    for (int j = 0; j < 16; j++) {
        CP_WAIT(1);
        __syncthreads();

        // S = Q @ K^T
        float sa[8][4];
        #pragma unroll
        for (int tj = 0; tj < 8; tj++)
            #pragma unroll
            for (int r = 0; r < 4; r++) sa[tj][r] = 0.f;
        #pragma unroll
        for (int k16 = 0; k16 < 64; k16 += 16) {
            unsigned af[4];
            ldsm_x4(af[0], af[1], af[2], af[3], Qb + qoff + k16 * 2);
            unsigned bf[8][2];
            #pragma unroll
            for (int tp = 0; tp < 4; tp++)
                ldsm_x4(bf[2*tp][0], bf[2*tp][1], bf[2*tp+1][0], bf[2*tp+1][1],
                        Kb + koff + tp * (16 * FP * 2) + k16 * 2);
            #pragma unroll
            for (int tj = 0; tj < 8; tj++)
                mma_f16(sa[tj], af, bf[tj]);
        }

        // Online softmax (fp32)
        float mx0 = -1e30f, mx1 = -1e30f;
        #pragma unroll
        for (int tj = 0; tj < 8; tj++) {
            sa[tj][0] *= 0.125f; sa[tj][1] *= 0.125f;
            sa[tj][2] *= 0.125f; sa[tj][3] *= 0.125f;
            mx0 = fmaxf(mx0, fmaxf(sa[tj][0], sa[tj][1]));
            mx1 = fmaxf(mx1, fmaxf(sa[tj][2], sa[tj][3]));
        }
        mx0 = fmaxf(mx0, __shfl_xor_sync(0xffffffffu, mx0, 1));
        mx0 = fmaxf(mx0, __shfl_xor_sync(0xffffffffu, mx0, 2));
        mx1 = fmaxf(mx1, __shfl_xor_sync(0xffffffffu, mx1, 1));
        mx1 = fmaxf(mx1, __shfl_xor_sync(0xffffffffu, mx1, 2));
        float mn0 = fmaxf(m0, mx0), mn1 = fmaxf(m1, mx1);
        float a0 = __expf(m0 - mn0), a1 = __expf(m1 - mn1);
        float s0 = 0.f, s1 = 0.f;
        #pragma unroll
        for (int tj = 0; tj < 8; tj++) {
            float p0 = __expf(sa[tj][0] - mn0);
            float p1 = __expf(sa[tj][1] - mn0);
            float p2 = __expf(sa[tj][2] - mn1);
            float p3 = __expf(sa[tj][3] - mn1);
            s0 += p0 + p1; s1 += p2 + p3;
            *(__half2*)(Ps + (warp_m + g) * FP + tj * 8 + 2 * tg) =
                __floats2half2_rn(p0, p1);
            *(__half2*)(Ps + (warp_m + g + 8) * FP + tj * 8 + 2 * tg) =
                __floats2half2_rn(p2, p3);
            oa[tj][0] *= a0; oa[tj][1] *= a0;
            oa[tj][2] *= a1; oa[tj][3] *= a1;
        }
        s0 += __shfl_xor_sync(0xffffffffu, s0, 1);
        s0 += __shfl_xor_sync(0xffffffffu, s0, 2);
        s1 += __shfl_xor_sync(0xffffffffu, s1, 1);
        s1 += __shfl_xor_sync(0xffffffffu, s1, 2);
        l0 = l0 * a0 + s0; l1 = l1 * a1 + s1;
        m0 = mn0; m1 = mn1;

        __syncthreads();                 // Ks consumed; Ps visible
        if (j < 15) issueK(j + 1);
        if (j < 15) { CP_WAIT(1); } else { CP_WAIT(0); }   // V_j arrived
        __syncthreads();

        // O += P @ V   (V via ldmatrix.trans)
        #pragma unroll
        for (int k16 = 0; k16 < 64; k16 += 16) {
            unsigned af[4];
            ldsm_x4(af[0], af[1], af[2], af[3], Pb + qoff + k16 * 2);
            unsigned bf[8][2];
            #pragma unroll
            for (int tp = 0; tp < 4; tp++)
                ldsm_x4_t(bf[2*tp][0], bf[2*tp][1], bf[2*tp+1][0], bf[2*tp+1][1],
                          Vb + voff + k16 * (FP * 2) + tp * 32);
            #pragma unroll
            for (int tj = 0; tj < 8; tj++)
                mma_f16(oa[tj], af, bf[tj]);
        }
        __syncthreads();                 // Vs consumed
        if (j < 15) issueV(j + 1);
    }

    // Normalize, write fp16 O
    float i0 = 1.f / l0, i1 = 1.f / l1;
    int r0 = q0 + warp_m + g, r1 = r0 + 8;
    __half* Ob = O + (size_t)b * NN_TOK * INNER + hd * DH;
    #pragma unroll
    for (int tj = 0; tj < 8; tj++) {
        int cc = tj * 8 + 2 * tg;
        *(__half2*)(Ob + (size_t)r0 * INNER + cc) =
            __floats2half2_rn(oa[tj][0] * i0, oa[tj][1] * i0);
        *(__half2*)(Ob + (size_t)r1 * INNER + cc) =
            __floats2half2_rn(oa[tj][2] * i1, oa[tj][3] * i1);
    }
}

// ---------------------------------------------------------------------------
extern "C" void kernel_launch(void* const* d_in, const int* in_sizes, int n_in,
                              void* d_out, int out_size) {
    const float* x      = (const float*)d_in[0];
    const float* w_conv = (const float*)d_in[1];
    const float* b_conv = (const float*)d_in[2];
    const float* pos    = (const float*)d_in[3];
    const float* ln1_w  = (const float*)d_in[4];
    const float* ln1_b  = (const float*)d_in[5];
    const float* qkv_w  = (const float*)d_in[6];
    const float* out_w  = (const float*)d_in[7];
    const float* out_b  = (const float*)d_in[8];
    const float* ln2_w  = (const float*)d_in[9];
    const float* ln2_b  = (const float*)d_in[10];
    const float* w1     = (const float*)d_in[11];
    const float* b1     = (const float*)d_in[12];
    const float* w2     = (const float*)d_in[13];
    const float* b2     = (const float*)d_in[14];

    float* h;
    __half *y, *qkv, *o, *mlp, *qw, *ow, *W1p, *W2p;
    cudaGetSymbolAddress((void**)&h,   g_h);
    cudaGetSymbolAddress((void**)&y,   g_y);
    cudaGetSymbolAddress((void**)&qkv, g_qkv);
    cudaGetSymbolAddress((void**)&o,   g_o);
    cudaGetSymbolAddress((void**)&mlp, g_mlp);
    cudaGetSymbolAddress((void**)&qw,  g_qw);
    cudaGetSymbolAddress((void**)&ow,  g_ow);
    cudaGetSymbolAddress((void**)&W1p, g_w1);
    cudaGetSymbolAddress((void**)&W2p, g_w2);

    static bool attrs_done = false;
    if (!attrs_done) {
        attrs_done = true;
        cudaFuncSetAttribute(hgemm<0,0,0,1>, cudaFuncAttributeMaxDynamicSharedMemorySize, GEMM_SMEM);
        cudaFuncSetAttribute(hgemm<1,0,1,0>, cudaFuncAttributeMaxDynamicSharedMemorySize, GEMM_SMEM);
        cudaFuncSetAttribute(hgemm<1,1,0,1>, cudaFuncAttributeMaxDynamicSharedMemorySize, GEMM_SMEM);
        cudaFuncSetAttribute(flash_attn,     cudaFuncAttributeMaxDynamicSharedMemorySize, FLASH_SMEM);
        cudaFuncSetAttribute(hgemm<0,0,0,1>, cudaFuncAttributePreferredSharedMemoryCarveout, 100);
        cudaFuncSetAttribute(hgemm<1,0,1,0>, cudaFuncAttributePreferredSharedMemoryCarveout, 100);
        cudaFuncSetAttribute(hgemm<1,1,0,1>, cudaFuncAttributePreferredSharedMemoryCarveout, 100);
        cudaFuncSetAttribute(flash_attn,     cudaFuncAttributePreferredSharedMemoryCarveout, 100);
    }

    // Prep: transpose + fp16-round all weights ([K][N] f32 -> [N][K] f16)
    {
        dim3 blk(32, 8);
        transpose_h_kernel<<<dim3(QKV_LD / 32, DD / 32, DEPTH), blk>>>(qkv_w, qw, DD, QKV_LD);
        transpose_h_kernel<<<dim3(DD / 32, INNER / 32, DEPTH), blk>>>(out_w, ow, INNER, DD);
        transpose_h_kernel<<<dim3(MLPD / 32, DD / 32, DEPTH), blk>>>(w1, W1p, DD, MLPD);
        transpose_h_kernel<<<dim3(DD / 32, MLPD / 32, DEPTH), blk>>>(w2, W2p, MLPD, DD);
    }

    patch_embed_kernel<<<M_ROWS, 256>>>(x, w_conv, b_conv, pos, h);

    for (int l = 0; l < DEPTH; l++) {
        const float*  l1w = ln1_w + (size_t)l * DD;
        const float*  l1b = ln1_b + (size_t)l * DD;
        const __half* qwl = qw + (size_t)l * DD * QKV_LD;
        const __half* owl = ow + (size_t)l * INNER * DD;
        const float*  ob  = out_b + (size_t)l * DD;
        const float*  l2w = ln2_w + (size_t)l * DD;
        const float*  l2b = ln2_b + (size_t)l * DD;
        const __half* W1l = W1p + (size_t)l * DD * MLPD;
        const float*  B1  = b1 + (size_t)l * MLPD;
        const __half* W2l = W2p + (size_t)l * MLPD * DD;
        const float*  B2  = b2 + (size_t)l * DD;

        // PreNorm + QKV projection (fp16 out feeds attention)
        ln_kernel<<<M_ROWS, 256>>>(h, l1w, l1b, y);
        hgemm<0,0,0,1><<<dim3(QKV_LD / 128, M_ROWS / 128), 256, GEMM_SMEM>>>(
            y, qwl, nullptr, nullptr, qkv, DD, QKV_LD);

        // Fused flash attention (fp16)
        flash_attn<<<dim3(NN_TOK / 128, BB * HEADS), 256, FLASH_SMEM>>>(qkv, o);

        // Output projection + residual (fp32 out into h)
        hgemm<1,0,1,0><<<dim3(DD / 128, M_ROWS / 128), 256, GEMM_SMEM>>>(
            o, owl, ob, h, h, INNER, DD);

        // PreNorm + FFN
        ln_kernel<<<M_ROWS, 256>>>(h, l2w, l2b, y);
        hgemm<1,1,0,1><<<dim3(MLPD / 128, M_ROWS / 128), 256, GEMM_SMEM>>>(
            y, W1l, B1, nullptr, mlp, DD, MLPD);
        void* cdst = (l == DEPTH - 1) ? d_out : (void*)h;
        hgemm<1,0,1,0><<<dim3(DD / 128, M_ROWS / 128), 256, GEMM_SMEM>>>(
            mlp, W2l, B2, h, cdst, MLPD, DD);
    }
}